// round 1
// baseline (speedup 1.0000x reference)
#include <cuda_runtime.h>
#include <math.h>

#define H_ 16
#define D_ 64
#define R_ 2048
#define S_ 64
#define B_ 2
#define E_ 1024
#define Z_ 64
#define SCALE_ 0.125f
#define MROWS (R_*B_)   /* 4096 */

// ---------------- scratch (device globals: allocation-free) ----------------
__device__ float g_tmp_q[MROWS*E_];
__device__ float g_tmp_k[MROWS*E_];
__device__ float g_tmp_v[MROWS*E_];
__device__ float g_q[B_*H_*R_*D_];
__device__ float g_k[B_*H_*R_*D_];
__device__ float g_v[B_*H_*R_*D_];
__device__ float g_r0[H_*Z_*D_];
__device__ float g_sumx2[B_*H_*S_*D_];
__device__ float g_k2[B_*H_*S_*D_];
__device__ float g_v2[B_*H_*S_*D_];
__device__ float g_attn[MROWS*E_];

// ---------------- fp32 GEMM: C[M,N] = A[M,K] @ W[K,N] + bias ----------------
// M=4096, N=1024, K=1024. BM=128, BN=64, BK=16, 256 threads, 8x4 microtile.
__global__ __launch_bounds__(256) void gemm_bias(const float* __restrict__ A,
        const float* __restrict__ W, const float* __restrict__ bias,
        float* __restrict__ C){
    const int K = 1024, N = 1024;
    __shared__ float As[16][128];
    __shared__ float Bs[16][64];
    int t  = threadIdx.x;
    int tx = t & 15, ty = t >> 4;
    int row0 = blockIdx.y * 128, n0 = blockIdx.x * 64;
    int ar = t >> 1, ac = (t & 1) * 8;
    int br = t >> 4, bc = (t & 15) * 4;
    float acc[8][4];
    #pragma unroll
    for (int i=0;i<8;i++)
        #pragma unroll
        for (int j=0;j<4;j++) acc[i][j]=0.f;

    float4 a0 = *(const float4*)&A[(row0+ar)*K + ac];
    float4 a1 = *(const float4*)&A[(row0+ar)*K + ac + 4];
    float4 b0 = *(const float4*)&W[br*N + n0 + bc];

    for (int k0 = 0; k0 < K; k0 += 16){
        As[ac+0][ar]=a0.x; As[ac+1][ar]=a0.y; As[ac+2][ar]=a0.z; As[ac+3][ar]=a0.w;
        As[ac+4][ar]=a1.x; As[ac+5][ar]=a1.y; As[ac+6][ar]=a1.z; As[ac+7][ar]=a1.w;
        *(float4*)&Bs[br][bc] = b0;
        __syncthreads();
        if (k0 + 16 < K){
            a0 = *(const float4*)&A[(row0+ar)*K + k0+16 + ac];
            a1 = *(const float4*)&A[(row0+ar)*K + k0+16 + ac + 4];
            b0 = *(const float4*)&W[(k0+16+br)*N + n0 + bc];
        }
        #pragma unroll
        for (int kk=0;kk<16;kk++){
            float ra[8], rb[4];
            #pragma unroll
            for (int i=0;i<8;i++) ra[i] = As[kk][ty*8+i];
            #pragma unroll
            for (int j=0;j<4;j++) rb[j] = Bs[kk][tx*4+j];
            #pragma unroll
            for (int i=0;i<8;i++)
                #pragma unroll
                for (int j=0;j<4;j++) acc[i][j] += ra[i]*rb[j];
        }
        __syncthreads();
    }
    #pragma unroll
    for (int i=0;i<8;i++){
        int r = row0 + ty*8 + i;
        #pragma unroll
        for (int j=0;j<4;j++)
            C[r*N + n0 + tx*4 + j] = acc[i][j] + bias[n0 + tx*4 + j];
    }
}

// -------- reorg (+ optional LN): tmp[rb][e] -> out[b][h][r][d], warp/row ----
__global__ __launch_bounds__(256) void reorg_kernel(const float* __restrict__ tmp,
        float* __restrict__ out, const float* __restrict__ gg,
        const float* __restrict__ bb, int mode){
    int wid  = blockIdx.x*8 + (threadIdx.x >> 5);
    int lane = threadIdx.x & 31;
    int rb = wid >> 4, h = wid & 15;
    const float* src = tmp + rb*E_ + h*64;
    float v0 = src[lane], v1 = src[32+lane];
    int b = rb & 1, r = rb >> 1;
    float* dst = out + (((b*H_ + h)*R_) + r)*64;
    if (mode == 0){
        dst[lane] = v0*SCALE_; dst[32+lane] = v1*SCALE_;
        return;
    }
    float s = v0 + v1;
    #pragma unroll
    for (int o=16;o;o>>=1) s += __shfl_xor_sync(0xffffffffu, s, o);
    float mean = s*(1.f/64.f);
    float d0 = v0-mean, d1 = v1-mean;
    float vv = d0*d0 + d1*d1;
    #pragma unroll
    for (int o=16;o;o>>=1) vv += __shfl_xor_sync(0xffffffffu, vv, o);
    float scl = rsqrtf(vv*(1.f/64.f) + 1e-5f);
    dst[lane]    = d0*scl*gg[lane]    + bb[lane];
    dst[32+lane] = d1*scl*gg[32+lane] + bb[32+lane];
}

// -------- r0[h][z][d] = sum_c rel_emb0[z][c] * Wr0[c][h*64+d] + br0 ---------
__global__ __launch_bounds__(64) void r0_kernel(const float* __restrict__ rel_emb0,
        const float* __restrict__ Wr0, const float* __restrict__ br0){
    int z = blockIdx.x >> 4, h = blockIdx.x & 15;
    int d = threadIdx.x;
    float a = br0[h*64+d];
    #pragma unroll 8
    for (int c=0;c<64;c++) a += rel_emb0[z*64+c]*Wr0[c*E_ + h*64 + d];
    g_r0[(h*Z_ + z)*64 + d] = a;
}

// shared layout (floats): q 64x68 | qr 64x65 | k 64x68 | v 64x68 | idx 64x64(int)
#define OFF_QR (64*68)
#define OFF_K  (OFF_QR + 64*65)
#define OFF_V  (OFF_K + 64*68)
#define OFF_I  (OFF_V + 64*68)
#define SMEM_ATTN_BYTES ((OFF_I + 64*64) * 4)

// -------------------- fused sum-token attention ----------------------------
// grid = B*H, 256 threads. 64 queries (s), 4 threads/query (16 dims each).
__global__ __launch_bounds__(256) void attn_sum_kernel(const int* __restrict__ tok,
        const float* __restrict__ emb_sum, const int* __restrict__ rel_idx){
    extern __shared__ float sm[];
    float* q_s  = sm;
    float* qr_s = sm + OFF_QR;
    float* k_s  = sm + OFF_K;
    float* v_s  = sm + OFF_V;
    int*   idx_s = (int*)(sm + OFF_I);
    int t = threadIdx.x, qi = t>>2, sub = t&3;
    int bh = blockIdx.x;
    int b = bh >> 4, h = bh & 15;

    {   // load sum_q tile (gather + scale) and r0 slice
        int token = tok[b*S_ + qi];
        const float4* src = (const float4*)(emb_sum + token*E_ + h*64);
        const float4* r0  = (const float4*)(g_r0 + (h*Z_ + qi)*64);
        #pragma unroll
        for (int j=0;j<4;j++){
            float4 v = src[sub*4+j];
            v.x*=SCALE_; v.y*=SCALE_; v.z*=SCALE_; v.w*=SCALE_;
            *(float4*)&q_s[qi*68 + sub*16 + j*4] = v;
            *(float4*)&k_s[qi*68 + sub*16 + j*4] = r0[sub*4+j];
        }
    }
    __syncthreads();
    // qr_s[qi][z] = q[qi] . r0[z]
    for (int z = sub*16; z < sub*16+16; z++){
        float a = 0.f;
        #pragma unroll
        for (int j=0;j<16;j++){
            float4 qa = *(const float4*)&q_s[qi*68 + j*4];
            float4 rb = *(const float4*)&k_s[z*68 + j*4];
            a += qa.x*rb.x + qa.y*rb.y + qa.z*rb.z + qa.w*rb.w;
        }
        qr_s[qi*65 + z] = a;
    }

    float m = -1e30f, l = 0.f;
    float acc[16];
    #pragma unroll
    for (int j=0;j<16;j++) acc[j]=0.f;

    const float* kb = g_k + (size_t)bh*R_*64;
    const float* vb = g_v + (size_t)bh*R_*64;
    const int* idxrow = rel_idx + (size_t)(b*(S_+R_) + qi)*R_;

    for (int kt = 0; kt < R_/64; kt++){
        __syncthreads();
        int k0 = kt*64;
        const float4* ks = (const float4*)(kb + (k0+qi)*64);
        const float4* vs = (const float4*)(vb + (k0+qi)*64);
        #pragma unroll
        for (int j=0;j<4;j++){
            *(float4*)&k_s[qi*68 + sub*16 + j*4] = ks[sub*4+j];
            *(float4*)&v_s[qi*68 + sub*16 + j*4] = vs[sub*4+j];
        }
        const int4* ii = (const int4*)(idxrow + k0);
        #pragma unroll
        for (int j=0;j<4;j++) ((int4*)&idx_s[qi*64 + sub*16])[j] = ii[sub*4+j];
        __syncthreads();
        #pragma unroll 4
        for (int kk=0;kk<64;kk++){
            float part = 0.f;
            #pragma unroll
            for (int j=0;j<4;j++){
                float4 qa = *(const float4*)&q_s[qi*68 + sub*16 + j*4];
                float4 kv = *(const float4*)&k_s[kk*68 + sub*16 + j*4];
                part += qa.x*kv.x + qa.y*kv.y + qa.z*kv.z + qa.w*kv.w;
            }
            part += __shfl_xor_sync(0xffffffffu, part, 1);
            part += __shfl_xor_sync(0xffffffffu, part, 2);
            float sc = part + qr_s[qi*65 + idx_s[qi*64+kk]];
            if (sc > m){
                float f = __expf(m - sc);
                l *= f;
                #pragma unroll
                for (int j=0;j<16;j++) acc[j]*=f;
                m = sc;
            }
            float p = __expf(sc - m);
            l += p;
            #pragma unroll
            for (int j=0;j<4;j++){
                float4 vv = *(const float4*)&v_s[kk*68 + sub*16 + j*4];
                acc[j*4+0] += p*vv.x; acc[j*4+1] += p*vv.y;
                acc[j*4+2] += p*vv.z; acc[j*4+3] += p*vv.w;
            }
        }
    }
    float inv = 1.f/l;
    float* out = g_sumx2 + (bh*S_ + qi)*64 + sub*16;
    #pragma unroll
    for (int j=0;j<16;j++) out[j] = acc[j]*inv;
}

// -------- per-row (b,h,s) projections sum_k2/sum_v2 with LN ----------------
__global__ __launch_bounds__(64) void k2v2_kernel(const float* __restrict__ Wk2,
        const float* __restrict__ bk2, const float* __restrict__ Wv2,
        const float* __restrict__ bv2, const float* __restrict__ g1,
        const float* __restrict__ b1, const float* __restrict__ g2,
        const float* __restrict__ b2){
    __shared__ float xr[64];
    __shared__ float red[2];
    int row = blockIdx.x, t = threadIdx.x;
    xr[t] = g_sumx2[row*64 + t];
    __syncthreads();
    #pragma unroll
    for (int pass=0; pass<2; pass++){
        const float* W  = pass ? Wv2 : Wk2;
        const float* bb = pass ? bv2 : bk2;
        const float* gg = pass ? g2  : g1;
        const float* bt = pass ? b2  : b1;
        float* outp     = pass ? g_v2 : g_k2;
        float a = bb[t];
        #pragma unroll 8
        for (int j=0;j<64;j++) a += xr[j]*W[j*64+t];
        float s = a;
        #pragma unroll
        for (int o=16;o;o>>=1) s += __shfl_xor_sync(0xffffffffu, s, o);
        if ((t&31)==0) red[t>>5] = s;
        __syncthreads();
        float mean = (red[0]+red[1]) * (1.f/64.f);
        __syncthreads();
        float dv = a - mean;
        float v2 = dv*dv;
        #pragma unroll
        for (int o=16;o;o>>=1) v2 += __shfl_xor_sync(0xffffffffu, v2, o);
        if ((t&31)==0) red[t>>5] = v2;
        __syncthreads();
        float var = (red[0]+red[1]) * (1.f/64.f);
        __syncthreads();
        outp[row*64 + t] = dv*rsqrtf(var+1e-5f)*gg[t] + bt[t];
    }
}

// -------------------- fused main attention ---------------------------------
// grid (R/64, H, B), 256 threads. keys = [sum_k2 (64, no bias), reg_k (2048, bias)]
__global__ __launch_bounds__(256) void attn_main_kernel(const int* __restrict__ rel_idx){
    extern __shared__ float sm[];
    float* q_s  = sm;
    float* qr_s = sm + OFF_QR;
    float* k_s  = sm + OFF_K;
    float* v_s  = sm + OFF_V;
    int*   idx_s = (int*)(sm + OFF_I);
    int t = threadIdx.x, qi = t>>2, sub = t&3;
    int b = blockIdx.z, h = blockIdx.y;
    int q0 = blockIdx.x * 64;
    int bh = b*H_ + h;
    int q = q0 + qi;

    {   // q tile + r0 slice
        const float4* qsrc = (const float4*)(g_q + ((size_t)bh*R_ + q)*64);
        const float4* r0   = (const float4*)(g_r0 + (h*Z_ + qi)*64);
        #pragma unroll
        for (int j=0;j<4;j++){
            *(float4*)&q_s[qi*68 + sub*16 + j*4] = qsrc[sub*4+j];
            *(float4*)&k_s[qi*68 + sub*16 + j*4] = r0[sub*4+j];
        }
    }
    __syncthreads();
    for (int z = sub*16; z < sub*16+16; z++){
        float a = 0.f;
        #pragma unroll
        for (int j=0;j<16;j++){
            float4 qa = *(const float4*)&q_s[qi*68 + j*4];
            float4 rb = *(const float4*)&k_s[z*68 + j*4];
            a += qa.x*rb.x + qa.y*rb.y + qa.z*rb.z + qa.w*rb.w;
        }
        qr_s[qi*65 + z] = a;
    }

    float m = -1e30f, l = 0.f;
    float acc[16];
    #pragma unroll
    for (int j=0;j<16;j++) acc[j]=0.f;

    // ---- sum keys (no rel bias) ----
    __syncthreads();
    {
        const float4* ks = (const float4*)(g_k2 + (bh*S_ + qi)*64);
        const float4* vs = (const float4*)(g_v2 + (bh*S_ + qi)*64);
        #pragma unroll
        for (int j=0;j<4;j++){
            *(float4*)&k_s[qi*68 + sub*16 + j*4] = ks[sub*4+j];
            *(float4*)&v_s[qi*68 + sub*16 + j*4] = vs[sub*4+j];
        }
        __syncthreads();
        #pragma unroll 4
        for (int kk=0;kk<64;kk++){
            float part = 0.f;
            #pragma unroll
            for (int j=0;j<4;j++){
                float4 qa = *(const float4*)&q_s[qi*68 + sub*16 + j*4];
                float4 kv = *(const float4*)&k_s[kk*68 + sub*16 + j*4];
                part += qa.x*kv.x + qa.y*kv.y + qa.z*kv.z + qa.w*kv.w;
            }
            part += __shfl_xor_sync(0xffffffffu, part, 1);
            part += __shfl_xor_sync(0xffffffffu, part, 2);
            float sc = part;
            if (sc > m){
                float f = __expf(m - sc);
                l *= f;
                #pragma unroll
                for (int j=0;j<16;j++) acc[j]*=f;
                m = sc;
            }
            float p = __expf(sc - m);
            l += p;
            #pragma unroll
            for (int j=0;j<4;j++){
                float4 vv = *(const float4*)&v_s[kk*68 + sub*16 + j*4];
                acc[j*4+0] += p*vv.x; acc[j*4+1] += p*vv.y;
                acc[j*4+2] += p*vv.z; acc[j*4+3] += p*vv.w;
            }
        }
    }

    // ---- reg keys (rel bias) ----
    const float* kb = g_k + (size_t)bh*R_*64;
    const float* vb = g_v + (size_t)bh*R_*64;
    const int* idxrow = rel_idx + (size_t)(b*(S_+R_) + S_ + q)*R_;
    for (int kt = 0; kt < R_/64; kt++){
        __syncthreads();
        int k0 = kt*64;
        const float4* ks = (const float4*)(kb + (k0+qi)*64);
        const float4* vs = (const float4*)(vb + (k0+qi)*64);
        #pragma unroll
        for (int j=0;j<4;j++){
            *(float4*)&k_s[qi*68 + sub*16 + j*4] = ks[sub*4+j];
            *(float4*)&v_s[qi*68 + sub*16 + j*4] = vs[sub*4+j];
        }
        const int4* ii = (const int4*)(idxrow + k0);
        #pragma unroll
        for (int j=0;j<4;j++) ((int4*)&idx_s[qi*64 + sub*16])[j] = ii[sub*4+j];
        __syncthreads();
        #pragma unroll 4
        for (int kk=0;kk<64;kk++){
            float part = 0.f;
            #pragma unroll
            for (int j=0;j<4;j++){
                float4 qa = *(const float4*)&q_s[qi*68 + sub*16 + j*4];
                float4 kv = *(const float4*)&k_s[kk*68 + sub*16 + j*4];
                part += qa.x*kv.x + qa.y*kv.y + qa.z*kv.z + qa.w*kv.w;
            }
            part += __shfl_xor_sync(0xffffffffu, part, 1);
            part += __shfl_xor_sync(0xffffffffu, part, 2);
            float sc = part + qr_s[qi*65 + idx_s[qi*64+kk]];
            if (sc > m){
                float f = __expf(m - sc);
                l *= f;
                #pragma unroll
                for (int j=0;j<16;j++) acc[j]*=f;
                m = sc;
            }
            float p = __expf(sc - m);
            l += p;
            #pragma unroll
            for (int j=0;j<4;j++){
                float4 vv = *(const float4*)&v_s[kk*68 + sub*16 + j*4];
                acc[j*4+0] += p*vv.x; acc[j*4+1] += p*vv.y;
                acc[j*4+2] += p*vv.z; acc[j*4+3] += p*vv.w;
            }
        }
    }

    float inv = 1.f/l;
    float* out = g_attn + ((size_t)q*B_ + b)*E_ + h*64 + sub*16;
    #pragma unroll
    for (int j=0;j<4;j++){
        float4 o;
        o.x = acc[j*4+0]*inv; o.y = acc[j*4+1]*inv;
        o.z = acc[j*4+2]*inv; o.w = acc[j*4+3]*inv;
        *(float4*)&out[j*4] = o;
    }
}

// ---------------------------------------------------------------------------
extern "C" void kernel_launch(void* const* d_in, const int* in_sizes, int n_in,
                              void* d_out, int out_size){
    const float* reg_x   = (const float*)d_in[0];
    const int*   tok     = (const int*)d_in[1];
    const int*   rel_idx = (const int*)d_in[2];
    // d_in[3]=sum_len, d_in[4]=reg_len (compile-time constants here)
    const float* emb_sum  = (const float*)d_in[5];
    const float* rel_emb0 = (const float*)d_in[6];
    const float* Wq  = (const float*)d_in[7];  const float* bq  = (const float*)d_in[8];
    const float* Wk  = (const float*)d_in[9];  const float* bk  = (const float*)d_in[10];
    const float* Wv  = (const float*)d_in[11]; const float* bv  = (const float*)d_in[12];
    const float* Wr0 = (const float*)d_in[13]; const float* br0 = (const float*)d_in[14];
    const float* Wk2 = (const float*)d_in[15]; const float* bk2 = (const float*)d_in[16];
    const float* Wv2 = (const float*)d_in[17]; const float* bv2 = (const float*)d_in[18];
    const float* Wo  = (const float*)d_in[19]; const float* bo  = (const float*)d_in[20];
    const float* lnkg  = (const float*)d_in[21]; const float* lnkb  = (const float*)d_in[22];
    const float* lnvg  = (const float*)d_in[23]; const float* lnvb  = (const float*)d_in[24];
    const float* lnk2g = (const float*)d_in[25]; const float* lnk2b = (const float*)d_in[26];
    const float* lnv2g = (const float*)d_in[27]; const float* lnv2b = (const float*)d_in[28];
    float* out = (float*)d_out;

    cudaFuncSetAttribute(attn_sum_kernel,  cudaFuncAttributeMaxDynamicSharedMemorySize, SMEM_ATTN_BYTES);
    cudaFuncSetAttribute(attn_main_kernel, cudaFuncAttributeMaxDynamicSharedMemorySize, SMEM_ATTN_BYTES);

    float *tq, *tk, *tv, *gq, *gk, *gv, *gattn;
    cudaGetSymbolAddress((void**)&tq, g_tmp_q);
    cudaGetSymbolAddress((void**)&tk, g_tmp_k);
    cudaGetSymbolAddress((void**)&tv, g_tmp_v);
    cudaGetSymbolAddress((void**)&gq, g_q);
    cudaGetSymbolAddress((void**)&gk, g_k);
    cudaGetSymbolAddress((void**)&gv, g_v);
    cudaGetSymbolAddress((void**)&gattn, g_attn);

    dim3 ggrid(E_/64, MROWS/128);   // (16, 32)
    gemm_bias<<<ggrid, 256>>>(reg_x, Wq, bq, tq);
    gemm_bias<<<ggrid, 256>>>(reg_x, Wk, bk, tk);
    gemm_bias<<<ggrid, 256>>>(reg_x, Wv, bv, tv);

    reorg_kernel<<<MROWS*H_/8, 256>>>(tq, gq, (const float*)0, (const float*)0, 0);
    reorg_kernel<<<MROWS*H_/8, 256>>>(tk, gk, lnkg, lnkb, 1);
    reorg_kernel<<<MROWS*H_/8, 256>>>(tv, gv, lnvg, lnvb, 1);

    r0_kernel<<<Z_*H_, 64>>>(rel_emb0, Wr0, br0);

    attn_sum_kernel<<<B_*H_, 256, SMEM_ATTN_BYTES>>>(tok, emb_sum, rel_idx);

    k2v2_kernel<<<B_*H_*S_, 64>>>(Wk2, bk2, Wv2, bv2, lnk2g, lnk2b, lnv2g, lnv2b);

    attn_main_kernel<<<dim3(R_/64, H_, B_), 256, SMEM_ATTN_BYTES>>>(rel_idx);

    gemm_bias<<<ggrid, 256>>>(gattn, Wo, bo, out);
}

// round 2
// speedup vs baseline: 2.8904x; 2.8904x over previous
#include <cuda_runtime.h>
#include <math.h>

#define H_ 16
#define D_ 64
#define R_ 2048
#define S_ 64
#define B_ 2
#define E_ 1024
#define Z_ 64
#define SCALE_ 0.125f
#define MROWS (R_*B_)   /* 4096 */
#define SPLITS 8

// ---------------- scratch (device globals: allocation-free) ----------------
__device__ float g_tmp_q[MROWS*E_];
__device__ float g_tmp_k[MROWS*E_];
__device__ float g_tmp_v[MROWS*E_];
__device__ float g_q[B_*H_*R_*D_];
__device__ float g_k[B_*H_*R_*D_];
__device__ float g_v[B_*H_*R_*D_];
__device__ float g_r0[H_*Z_*D_];
__device__ float g_sumx2[B_*H_*S_*D_];
__device__ float g_k2[B_*H_*S_*D_];
__device__ float g_v2[B_*H_*S_*D_];
__device__ float g_attn[MROWS*E_];
__device__ float g_pacc[B_*H_*SPLITS*S_*D_];
__device__ float g_pm[B_*H_*SPLITS*S_];
__device__ float g_pl[B_*H_*SPLITS*S_];

// ---------------- packed f32x2 helpers -------------------------------------
typedef unsigned long long u64;
__device__ __forceinline__ u64 f2pack(float lo, float hi){
    u64 r; asm("mov.b64 %0,{%1,%2};" : "=l"(r) : "f"(lo), "f"(hi)); return r;
}
__device__ __forceinline__ u64 f2splat(float x){ return f2pack(x,x); }
__device__ __forceinline__ u64 ffma2(u64 a, u64 b, u64 c){
    u64 d; asm("fma.rn.f32x2 %0,%1,%2,%3;" : "=l"(d) : "l"(a), "l"(b), "l"(c)); return d;
}
__device__ __forceinline__ u64 fmul2(u64 a, u64 b){
    u64 d; asm("mul.rn.f32x2 %0,%1,%2;" : "=l"(d) : "l"(a), "l"(b)); return d;
}
__device__ __forceinline__ void f2unpack(u64 v, float& lo, float& hi){
    asm("mov.b64 {%0,%1},%2;" : "=f"(lo), "=f"(hi) : "l"(v));
}

// ---------------- fp32 GEMM (FFMA2): C[M,N] = A[M,K]@W[K,N] + bias ---------
// M=4096, N=1024, K=1024. BM=128, BN=128, BK=16, 256 threads, 8x8 microtile.
__global__ __launch_bounds__(256,2) void gemm_bias(const float* __restrict__ A,
        const float* __restrict__ W, const float* __restrict__ bias,
        float* __restrict__ C){
    const int K = 1024, N = 1024;
    __shared__ float As[16][132];
    __shared__ float Bs[16][128];
    int t = threadIdx.x;
    int tx = t & 15, ty = t >> 4;
    int row0 = blockIdx.y * 128, n0 = blockIdx.x * 128;
    int ar = t >> 1, ac = (t & 1) * 8;
    int br = t >> 5, bc = (t & 31) * 4;
    u64 acc[8][4];
    #pragma unroll
    for (int i=0;i<8;i++)
        #pragma unroll
        for (int j=0;j<4;j++) acc[i][j]=0ull;

    float4 a0 = *(const float4*)&A[(row0+ar)*K + ac];
    float4 a1 = *(const float4*)&A[(row0+ar)*K + ac + 4];
    float4 b0 = *(const float4*)&W[br*N + n0 + bc];
    float4 b1 = *(const float4*)&W[(br+8)*N + n0 + bc];

    for (int k0 = 0; k0 < K; k0 += 16){
        As[ac+0][ar]=a0.x; As[ac+1][ar]=a0.y; As[ac+2][ar]=a0.z; As[ac+3][ar]=a0.w;
        As[ac+4][ar]=a1.x; As[ac+5][ar]=a1.y; As[ac+6][ar]=a1.z; As[ac+7][ar]=a1.w;
        *(float4*)&Bs[br][bc]   = b0;
        *(float4*)&Bs[br+8][bc] = b1;
        __syncthreads();
        if (k0 + 16 < K){
            a0 = *(const float4*)&A[(row0+ar)*K + k0+16 + ac];
            a1 = *(const float4*)&A[(row0+ar)*K + k0+16 + ac + 4];
            b0 = *(const float4*)&W[(k0+16+br)*N + n0 + bc];
            b1 = *(const float4*)&W[(k0+24+br)*N + n0 + bc];
        }
        #pragma unroll
        for (int kk=0;kk<16;kk++){
            float4 x0 = *(const float4*)&As[kk][ty*8];
            float4 x1 = *(const float4*)&As[kk][ty*8+4];
            float4 y0 = *(const float4*)&Bs[kk][tx*8];
            float4 y1 = *(const float4*)&Bs[kk][tx*8+4];
            u64 p0=f2pack(y0.x,y0.y), p1=f2pack(y0.z,y0.w);
            u64 p2=f2pack(y1.x,y1.y), p3=f2pack(y1.z,y1.w);
            float xa[8]={x0.x,x0.y,x0.z,x0.w,x1.x,x1.y,x1.z,x1.w};
            #pragma unroll
            for (int i=0;i<8;i++){
                u64 s = f2splat(xa[i]);
                acc[i][0]=ffma2(s,p0,acc[i][0]);
                acc[i][1]=ffma2(s,p1,acc[i][1]);
                acc[i][2]=ffma2(s,p2,acc[i][2]);
                acc[i][3]=ffma2(s,p3,acc[i][3]);
            }
        }
        __syncthreads();
    }
    #pragma unroll
    for (int i=0;i<8;i++){
        int r = row0 + ty*8 + i;
        float o[8];
        f2unpack(acc[i][0],o[0],o[1]); f2unpack(acc[i][1],o[2],o[3]);
        f2unpack(acc[i][2],o[4],o[5]); f2unpack(acc[i][3],o[6],o[7]);
        #pragma unroll
        for (int j=0;j<8;j++) o[j] += bias[n0 + tx*8 + j];
        *(float4*)&C[r*N + n0 + tx*8]   = make_float4(o[0],o[1],o[2],o[3]);
        *(float4*)&C[r*N + n0 + tx*8+4] = make_float4(o[4],o[5],o[6],o[7]);
    }
}

// -------- reorg (+ optional LN): tmp[rb][e] -> out[b][h][r][d], warp/row ----
__global__ __launch_bounds__(256) void reorg_kernel(const float* __restrict__ tmp,
        float* __restrict__ out, const float* __restrict__ gg,
        const float* __restrict__ bb, int mode){
    int wid  = blockIdx.x*8 + (threadIdx.x >> 5);
    int lane = threadIdx.x & 31;
    int rb = wid >> 4, h = wid & 15;
    const float* src = tmp + rb*E_ + h*64;
    float v0 = src[lane], v1 = src[32+lane];
    int b = rb & 1, r = rb >> 1;
    float* dst = out + (((b*H_ + h)*R_) + r)*64;
    if (mode == 0){
        dst[lane] = v0*SCALE_; dst[32+lane] = v1*SCALE_;
        return;
    }
    float s = v0 + v1;
    #pragma unroll
    for (int o=16;o;o>>=1) s += __shfl_xor_sync(0xffffffffu, s, o);
    float mean = s*(1.f/64.f);
    float d0 = v0-mean, d1 = v1-mean;
    float vv = d0*d0 + d1*d1;
    #pragma unroll
    for (int o=16;o;o>>=1) vv += __shfl_xor_sync(0xffffffffu, vv, o);
    float scl = rsqrtf(vv*(1.f/64.f) + 1e-5f);
    dst[lane]    = d0*scl*gg[lane]    + bb[lane];
    dst[32+lane] = d1*scl*gg[32+lane] + bb[32+lane];
}

// -------- r0[h][z][d] = sum_c rel_emb0[z][c] * Wr0[c][h*64+d] + br0 ---------
__global__ __launch_bounds__(64) void r0_kernel(const float* __restrict__ rel_emb0,
        const float* __restrict__ Wr0, const float* __restrict__ br0){
    int z = blockIdx.x >> 4, h = blockIdx.x & 15;
    int d = threadIdx.x;
    float a = br0[h*64+d];
    #pragma unroll 8
    for (int c=0;c<64;c++) a += rel_emb0[z*64+c]*Wr0[c*E_ + h*64 + d];
    g_r0[(h*Z_ + z)*64 + d] = a;
}

// ---------------- tiled flash attention, shared layout (floats) -------------
// q_t[64d][68] | k_t[64d][68] | v[64k][68] | SP[64][68] | qr[64q][68] |
// idx[64q][64] int | m[64] | l[64] | fac[64]
#define AQT 0
#define AKT 4352
#define AV  8704
#define ASP 13056
#define AQR 17408
#define AIX 21760
#define AM  25856
#define AL  25920
#define AF  25984
#define ATTN_SMEM_F 26048
#define ATTN_SMEM_BYTES (ATTN_SMEM_F*4)

// score microtile: compute sacc[4q][2 kpairs] from q_t x k_t over 64 dims
#define SCORE_TILE(DST, STRIDE_WR)                                          \
    {                                                                       \
        u64 sacc[4][2];                                                     \
        _Pragma("unroll")                                                   \
        for (int i=0;i<4;i++){ sacc[i][0]=0ull; sacc[i][1]=0ull; }          \
        _Pragma("unroll 4")                                                 \
        for (int kk=0;kk<64;kk++){                                          \
            float4 a = *(const float4*)&sm[AQT + kk*68 + ty*4];             \
            float4 bk = *(const float4*)&sm[AKT + kk*68 + tx*4];            \
            u64 b01=f2pack(bk.x,bk.y), b23=f2pack(bk.z,bk.w);               \
            float aa[4]={a.x,a.y,a.z,a.w};                                  \
            _Pragma("unroll")                                               \
            for (int i=0;i<4;i++){                                          \
                u64 s = f2splat(aa[i]);                                     \
                sacc[i][0]=ffma2(s,b01,sacc[i][0]);                         \
                sacc[i][1]=ffma2(s,b23,sacc[i][1]);                         \
            }                                                               \
        }                                                                   \
        _Pragma("unroll")                                                   \
        for (int i=0;i<4;i++){                                              \
            float s0,s1,s2,s3;                                              \
            f2unpack(sacc[i][0],s0,s1); f2unpack(sacc[i][1],s2,s3);         \
            *(float4*)&sm[(DST) + (ty*4+i)*(STRIDE_WR) + tx*4] =            \
                make_float4(s0,s1,s2,s3);                                   \
        }                                                                   \
    }

// softmax + P-transpose + state update for one 64-key tile
#define SOFTMAX_TILE(USE_BIAS)                                              \
    {                                                                       \
        int row = t>>2, c0 = (t&3)*16;                                      \
        float sv[16];                                                       \
        _Pragma("unroll")                                                   \
        for (int j=0;j<16;j+=4){                                            \
            float4 x = *(const float4*)&sm[ASP + row*68 + c0 + j];          \
            sv[j]=x.x; sv[j+1]=x.y; sv[j+2]=x.z; sv[j+3]=x.w;               \
        }                                                                   \
        if (USE_BIAS){                                                      \
            int* ix = (int*)&sm[AIX];                                       \
            _Pragma("unroll")                                               \
            for (int j=0;j<16;j++)                                          \
                sv[j] += sm[AQR + row*68 + ix[row*64 + c0 + j]];            \
        }                                                                   \
        float tm = sv[0];                                                   \
        _Pragma("unroll")                                                   \
        for (int j=1;j<16;j++) tm = fmaxf(tm, sv[j]);                       \
        tm = fmaxf(tm, __shfl_xor_sync(0xffffffffu, tm, 1));                \
        tm = fmaxf(tm, __shfl_xor_sync(0xffffffffu, tm, 2));                \
        float mold = sm[AM + row];                                          \
        float mnew = fmaxf(mold, tm);                                       \
        float p[16]; float rsum = 0.f;                                      \
        _Pragma("unroll")                                                   \
        for (int j=0;j<16;j++){ p[j] = __expf(sv[j]-mnew); rsum += p[j]; }  \
        rsum += __shfl_xor_sync(0xffffffffu, rsum, 1);                      \
        rsum += __shfl_xor_sync(0xffffffffu, rsum, 2);                      \
        __syncthreads();                                                    \
        _Pragma("unroll")                                                   \
        for (int j=0;j<16;j++) sm[ASP + (c0+j)*68 + row] = p[j];            \
        if ((t&3)==0){                                                      \
            float f = __expf(mold - mnew);                                  \
            sm[AF + row] = f;                                               \
            sm[AL + row] = sm[AL + row]*f + rsum;                           \
            sm[AM + row] = mnew;                                            \
        }                                                                   \
        __syncthreads();                                                    \
    }

// PV: rescale oacc by fac, accumulate P_t x V
#define PV_TILE()                                                           \
    {                                                                       \
        _Pragma("unroll")                                                   \
        for (int i=0;i<4;i++){                                              \
            u64 fs = f2splat(sm[AF + ty*4 + i]);                            \
            oacc[i][0]=fmul2(oacc[i][0],fs);                                \
            oacc[i][1]=fmul2(oacc[i][1],fs);                                \
        }                                                                   \
        _Pragma("unroll 4")                                                 \
        for (int kk=0;kk<64;kk++){                                          \
            float4 a = *(const float4*)&sm[ASP + kk*68 + ty*4];             \
            float4 bv = *(const float4*)&sm[AV + kk*68 + tx*4];             \
            u64 b01=f2pack(bv.x,bv.y), b23=f2pack(bv.z,bv.w);               \
            float aa[4]={a.x,a.y,a.z,a.w};                                  \
            _Pragma("unroll")                                               \
            for (int i=0;i<4;i++){                                          \
                u64 s = f2splat(aa[i]);                                     \
                oacc[i][0]=ffma2(s,b01,oacc[i][0]);                         \
                oacc[i][1]=ffma2(s,b23,oacc[i][1]);                         \
            }                                                               \
        }                                                                   \
    }

// scatter-transpose a 64x64 tile row (per-thread 16 floats) into [d][q] layout
#define LOAD_T(DSTOFF, SRCPTR)                                              \
    {                                                                       \
        const float* _s = (SRCPTR);                                         \
        _Pragma("unroll")                                                   \
        for (int e=0;e<16;e+=4){                                            \
            float4 x = *(const float4*)(_s + e);                            \
            sm[(DSTOFF) + (dseg+e+0)*68 + lrow] = x.x;                      \
            sm[(DSTOFF) + (dseg+e+1)*68 + lrow] = x.y;                      \
            sm[(DSTOFF) + (dseg+e+2)*68 + lrow] = x.z;                      \
            sm[(DSTOFF) + (dseg+e+3)*68 + lrow] = x.w;                      \
        }                                                                   \
    }

// -------------------- fused main attention ---------------------------------
// grid (R/64, H, B), 256 threads.
__global__ __launch_bounds__(256,2) void attn_main_kernel(const int* __restrict__ rel_idx){
    extern __shared__ float sm[];
    const int t = threadIdx.x, tx = t&15, ty = t>>4;
    const int b = blockIdx.z, h = blockIdx.y, bh = b*H_ + h;
    const int q0 = blockIdx.x * 64;
    const int lrow = t>>2, dseg = (t&3)*16;

    LOAD_T(AQT, g_q + ((size_t)bh*R_ + q0 + lrow)*64 + dseg);
    LOAD_T(AKT, g_r0 + (h*Z_ + lrow)*64 + dseg);
    if (t < 64){ sm[AM+t] = -1e30f; sm[AL+t] = 0.f; }
    __syncthreads();
    SCORE_TILE(AQR, 68);   // qr[q][z] = q . r0

    u64 oacc[4][2];
    #pragma unroll
    for (int i=0;i<4;i++){ oacc[i][0]=0ull; oacc[i][1]=0ull; }

    for (int kt=0; kt<33; kt++){
        __syncthreads();
        if (kt == 0){
            LOAD_T(AKT, g_k2 + ((size_t)bh*S_ + lrow)*64 + dseg);
            const float* vs = g_v2 + ((size_t)bh*S_ + lrow)*64 + dseg;
            #pragma unroll
            for (int e=0;e<16;e+=4)
                *(float4*)&sm[AV + lrow*68 + dseg + e] = *(const float4*)(vs+e);
        } else {
            int k0 = (kt-1)*64;
            LOAD_T(AKT, g_k + ((size_t)bh*R_ + k0 + lrow)*64 + dseg);
            const float* vs = g_v + ((size_t)bh*R_ + k0 + lrow)*64 + dseg;
            #pragma unroll
            for (int e=0;e<16;e+=4)
                *(float4*)&sm[AV + lrow*68 + dseg + e] = *(const float4*)(vs+e);
            const int4* is = (const int4*)(rel_idx +
                (size_t)(b*(S_+R_) + S_ + q0 + lrow)*R_ + k0 + dseg);
            int* ix = (int*)&sm[AIX];
            #pragma unroll
            for (int e=0;e<4;e++) ((int4*)&ix[lrow*64 + dseg])[e] = is[e];
        }
        __syncthreads();
        SCORE_TILE(ASP, 68);
        __syncthreads();
        if (kt == 0){ SOFTMAX_TILE(0); } else { SOFTMAX_TILE(1); }
        PV_TILE();
    }
    __syncthreads();
    #pragma unroll
    for (int i=0;i<4;i++){
        float inv = 1.f / sm[AL + ty*4 + i];
        float o0,o1,o2,o3;
        f2unpack(oacc[i][0],o0,o1); f2unpack(oacc[i][1],o2,o3);
        *(float4*)&g_attn[((size_t)(q0+ty*4+i)*B_ + b)*E_ + h*64 + tx*4] =
            make_float4(o0*inv,o1*inv,o2*inv,o3*inv);
    }
}

// -------------------- fused sum attention (split-K) -------------------------
// grid (B*H, SPLITS), 256 threads; each split covers 256 keys (4 tiles).
__global__ __launch_bounds__(256,2) void attn_sum_kernel(const int* __restrict__ tok,
        const float* __restrict__ emb_sum, const int* __restrict__ rel_idx){
    extern __shared__ float sm[];
    const int t = threadIdx.x, tx = t&15, ty = t>>4;
    const int bh = blockIdx.x, split = blockIdx.y;
    const int b = bh >> 4, h = bh & 15;
    const int lrow = t>>2, dseg = (t&3)*16;

    {   // gather + scale sum_q, transpose into q_t
        int token = tok[b*S_ + lrow];
        const float* qs = emb_sum + (size_t)token*E_ + h*64 + dseg;
        #pragma unroll
        for (int e=0;e<16;e+=4){
            float4 x = *(const float4*)(qs + e);
            sm[AQT + (dseg+e+0)*68 + lrow] = x.x*SCALE_;
            sm[AQT + (dseg+e+1)*68 + lrow] = x.y*SCALE_;
            sm[AQT + (dseg+e+2)*68 + lrow] = x.z*SCALE_;
            sm[AQT + (dseg+e+3)*68 + lrow] = x.w*SCALE_;
        }
    }
    LOAD_T(AKT, g_r0 + (h*Z_ + lrow)*64 + dseg);
    if (t < 64){ sm[AM+t] = -1e30f; sm[AL+t] = 0.f; }
    __syncthreads();
    SCORE_TILE(AQR, 68);

    u64 oacc[4][2];
    #pragma unroll
    for (int i=0;i<4;i++){ oacc[i][0]=0ull; oacc[i][1]=0ull; }

    for (int kt=0; kt<4; kt++){
        __syncthreads();
        int k0 = split*256 + kt*64;
        LOAD_T(AKT, g_k + ((size_t)bh*R_ + k0 + lrow)*64 + dseg);
        const float* vs = g_v + ((size_t)bh*R_ + k0 + lrow)*64 + dseg;
        #pragma unroll
        for (int e=0;e<16;e+=4)
            *(float4*)&sm[AV + lrow*68 + dseg + e] = *(const float4*)(vs+e);
        const int4* is = (const int4*)(rel_idx +
            (size_t)(b*(S_+R_) + lrow)*R_ + k0 + dseg);
        int* ix = (int*)&sm[AIX];
        #pragma unroll
        for (int e=0;e<4;e++) ((int4*)&ix[lrow*64 + dseg])[e] = is[e];
        __syncthreads();
        SCORE_TILE(ASP, 68);
        __syncthreads();
        SOFTMAX_TILE(1);
        PV_TILE();
    }
    __syncthreads();
    int pb = bh*SPLITS + split;
    #pragma unroll
    for (int i=0;i<4;i++){
        float o0,o1,o2,o3;
        f2unpack(oacc[i][0],o0,o1); f2unpack(oacc[i][1],o2,o3);
        *(float4*)&g_pacc[((size_t)pb*S_ + ty*4+i)*64 + tx*4] =
            make_float4(o0,o1,o2,o3);
    }
    if (t < 64){
        g_pm[pb*S_ + t] = sm[AM + t];
        g_pl[pb*S_ + t] = sm[AL + t];
    }
}

// -------- combine split-K partials -> g_sumx2 -------------------------------
__global__ __launch_bounds__(64) void combine_kernel(){
    int rowq = blockIdx.x;            // bh*64 + s
    int bh = rowq >> 6, s = rowq & 63;
    int d = threadIdx.x;
    float mv[SPLITS];
    float M = -1e30f;
    #pragma unroll
    for (int i=0;i<SPLITS;i++){
        mv[i] = g_pm[(bh*SPLITS + i)*S_ + s];
        M = fmaxf(M, mv[i]);
    }
    float L = 0.f, acc = 0.f;
    #pragma unroll
    for (int i=0;i<SPLITS;i++){
        float w = __expf(mv[i] - M);
        acc += w * g_pacc[((size_t)(bh*SPLITS + i)*S_ + s)*64 + d];
        L   += w * g_pl[(bh*SPLITS + i)*S_ + s];
    }
    g_sumx2[(bh*S_ + s)*64 + d] = acc / L;
}

// -------- per-row (b,h,s) projections sum_k2/sum_v2 with LN ----------------
__global__ __launch_bounds__(64) void k2v2_kernel(const float* __restrict__ Wk2,
        const float* __restrict__ bk2, const float* __restrict__ Wv2,
        const float* __restrict__ bv2, const float* __restrict__ g1,
        const float* __restrict__ b1, const float* __restrict__ g2,
        const float* __restrict__ b2){
    __shared__ float xr[64];
    __shared__ float red[2];
    int row = blockIdx.x, t = threadIdx.x;
    xr[t] = g_sumx2[row*64 + t];
    __syncthreads();
    #pragma unroll
    for (int pass=0; pass<2; pass++){
        const float* W  = pass ? Wv2 : Wk2;
        const float* bb = pass ? bv2 : bk2;
        const float* gg = pass ? g2  : g1;
        const float* bt = pass ? b2  : b1;
        float* outp     = pass ? g_v2 : g_k2;
        float a = bb[t];
        #pragma unroll 8
        for (int j=0;j<64;j++) a += xr[j]*W[j*64+t];
        float s = a;
        #pragma unroll
        for (int o=16;o;o>>=1) s += __shfl_xor_sync(0xffffffffu, s, o);
        if ((t&31)==0) red[t>>5] = s;
        __syncthreads();
        float mean = (red[0]+red[1]) * (1.f/64.f);
        __syncthreads();
        float dv = a - mean;
        float v2 = dv*dv;
        #pragma unroll
        for (int o=16;o;o>>=1) v2 += __shfl_xor_sync(0xffffffffu, v2, o);
        if ((t&31)==0) red[t>>5] = v2;
        __syncthreads();
        float var = (red[0]+red[1]) * (1.f/64.f);
        __syncthreads();
        outp[row*64 + t] = dv*rsqrtf(var+1e-5f)*gg[t] + bt[t];
    }
}

// ---------------------------------------------------------------------------
extern "C" void kernel_launch(void* const* d_in, const int* in_sizes, int n_in,
                              void* d_out, int out_size){
    const float* reg_x   = (const float*)d_in[0];
    const int*   tok     = (const int*)d_in[1];
    const int*   rel_idx = (const int*)d_in[2];
    const float* emb_sum  = (const float*)d_in[5];
    const float* rel_emb0 = (const float*)d_in[6];
    const float* Wq  = (const float*)d_in[7];  const float* bq  = (const float*)d_in[8];
    const float* Wk  = (const float*)d_in[9];  const float* bk  = (const float*)d_in[10];
    const float* Wv  = (const float*)d_in[11]; const float* bv  = (const float*)d_in[12];
    const float* Wr0 = (const float*)d_in[13]; const float* br0 = (const float*)d_in[14];
    const float* Wk2 = (const float*)d_in[15]; const float* bk2 = (const float*)d_in[16];
    const float* Wv2 = (const float*)d_in[17]; const float* bv2 = (const float*)d_in[18];
    const float* Wo  = (const float*)d_in[19]; const float* bo  = (const float*)d_in[20];
    const float* lnkg  = (const float*)d_in[21]; const float* lnkb  = (const float*)d_in[22];
    const float* lnvg  = (const float*)d_in[23]; const float* lnvb  = (const float*)d_in[24];
    const float* lnk2g = (const float*)d_in[25]; const float* lnk2b = (const float*)d_in[26];
    const float* lnv2g = (const float*)d_in[27]; const float* lnv2b = (const float*)d_in[28];
    float* out = (float*)d_out;

    cudaFuncSetAttribute(attn_sum_kernel,  cudaFuncAttributeMaxDynamicSharedMemorySize, ATTN_SMEM_BYTES);
    cudaFuncSetAttribute(attn_main_kernel, cudaFuncAttributeMaxDynamicSharedMemorySize, ATTN_SMEM_BYTES);

    float *tq, *tk, *tv, *gq, *gk, *gv, *gattn;
    cudaGetSymbolAddress((void**)&tq, g_tmp_q);
    cudaGetSymbolAddress((void**)&tk, g_tmp_k);
    cudaGetSymbolAddress((void**)&tv, g_tmp_v);
    cudaGetSymbolAddress((void**)&gq, g_q);
    cudaGetSymbolAddress((void**)&gk, g_k);
    cudaGetSymbolAddress((void**)&gv, g_v);
    cudaGetSymbolAddress((void**)&gattn, g_attn);

    dim3 ggrid(E_/128, MROWS/128);   // (8, 32)
    gemm_bias<<<ggrid, 256>>>(reg_x, Wq, bq, tq);
    gemm_bias<<<ggrid, 256>>>(reg_x, Wk, bk, tk);
    gemm_bias<<<ggrid, 256>>>(reg_x, Wv, bv, tv);

    reorg_kernel<<<MROWS*H_/8, 256>>>(tq, gq, (const float*)0, (const float*)0, 0);
    reorg_kernel<<<MROWS*H_/8, 256>>>(tk, gk, lnkg, lnkb, 1);
    reorg_kernel<<<MROWS*H_/8, 256>>>(tv, gv, lnvg, lnvb, 1);

    r0_kernel<<<Z_*H_, 64>>>(rel_emb0, Wr0, br0);

    attn_sum_kernel<<<dim3(B_*H_, SPLITS), 256, ATTN_SMEM_BYTES>>>(tok, emb_sum, rel_idx);
    combine_kernel<<<B_*H_*S_, 64>>>();
    k2v2_kernel<<<B_*H_*S_, 64>>>(Wk2, bk2, Wv2, bv2, lnk2g, lnk2b, lnv2g, lnv2b);

    attn_main_kernel<<<dim3(R_/64, H_, B_), 256, ATTN_SMEM_BYTES>>>(rel_idx);

    gemm_bias<<<ggrid, 256>>>(gattn, Wo, bo, out);
}

// round 3
// speedup vs baseline: 3.8100x; 1.3181x over previous
#include <cuda_runtime.h>
#include <math.h>

#define H_ 16
#define D_ 64
#define R_ 2048
#define S_ 64
#define B_ 2
#define E_ 1024
#define Z_ 64
#define SCALE_ 0.125f
#define MROWS (R_*B_)   /* 4096 */
#define SPLITS 8

// ---------------- scratch (device globals: allocation-free) ----------------
__device__ float g_tmp_q[MROWS*E_];
__device__ float g_tmp_k[MROWS*E_];
__device__ float g_tmp_v[MROWS*E_];
__device__ float g_q[B_*H_*R_*D_];
__device__ float g_k[B_*H_*R_*D_];
__device__ float g_v[B_*H_*R_*D_];
__device__ float g_r0[H_*Z_*D_];
__device__ float g_sumx2[B_*H_*S_*D_];
__device__ float g_k2[B_*H_*S_*D_];
__device__ float g_v2[B_*H_*S_*D_];
__device__ float g_attn[MROWS*E_];
__device__ float g_pacc[B_*H_*SPLITS*S_*D_];
__device__ float g_pm[B_*H_*SPLITS*S_];
__device__ float g_pl[B_*H_*SPLITS*S_];

// ---------------- tf32 helpers ---------------------------------------------
__device__ __forceinline__ unsigned cvt_tf32(float x){
    unsigned u; asm("cvt.rna.tf32.f32 %0, %1;" : "=r"(u) : "f"(x)); return u;
}
__device__ __forceinline__ void mma_tf32(float* c,
        unsigned a0, unsigned a1, unsigned a2, unsigned a3,
        unsigned b0, unsigned b1){
    asm volatile(
        "mma.sync.aligned.m16n8k8.row.col.f32.tf32.tf32.f32 "
        "{%0,%1,%2,%3},{%4,%5,%6,%7},{%8,%9},{%0,%1,%2,%3};"
        : "+f"(c[0]), "+f"(c[1]), "+f"(c[2]), "+f"(c[3])
        : "r"(a0), "r"(a1), "r"(a2), "r"(a3), "r"(b0), "r"(b1));
}

// ---------------- tf32 tensor-core GEMM ------------------------------------
// C[M,N] = A[M,1024] @ W[1024,N] + bias. Block 128x128, 256 thr, 8 warps.
// Warp tile 32m x 64n (2 m-frags x 8 n-frags), k-step 8, BK=32.
__global__ __launch_bounds__(256) void gemm_bias(const float* __restrict__ A,
        const float* __restrict__ W, const float* __restrict__ bias,
        float* __restrict__ C){
    const int K = 1024, N = 1024;
    __shared__ unsigned As[128*40];     // [row][k-permuted], stride 40
    __shared__ unsigned Bs[32*136];     // [k][n], stride 136
    int t = threadIdx.x, lane = t & 31, w = t >> 5;
    int wm = w >> 1, wn = w & 1;
    int tq = lane >> 2, te = lane & 3;
    int row0 = blockIdx.y * 128, n0 = blockIdx.x * 128;
    int ar = t >> 1, ah = (t & 1) * 16;
    int br = t >> 3, bc = (t & 7) * 16;

    float acc[2][8][4];
    #pragma unroll
    for (int m=0;m<2;m++)
        #pragma unroll
        for (int n=0;n<8;n++)
            #pragma unroll
            for (int j=0;j<4;j++) acc[m][n][j]=0.f;

    float4 apre[4], wpre[4];
    #pragma unroll
    for (int j=0;j<4;j++){
        apre[j] = *(const float4*)&A[(row0+ar)*K + ah + j*4];
        wpre[j] = *(const float4*)&W[br*N + n0 + bc + j*4];
    }

    for (int k0 = 0; k0 < K; k0 += 32){
        #pragma unroll
        for (int j=0;j<4;j++){
            int c = ah + j*4;
            int base = ar*40 + (c & ~7) + ((c>>2)&1);
            As[base+0]=cvt_tf32(apre[j].x); As[base+2]=cvt_tf32(apre[j].y);
            As[base+4]=cvt_tf32(apre[j].z); As[base+6]=cvt_tf32(apre[j].w);
            unsigned* bd = &Bs[br*136 + bc + j*4];
            bd[0]=cvt_tf32(wpre[j].x); bd[1]=cvt_tf32(wpre[j].y);
            bd[2]=cvt_tf32(wpre[j].z); bd[3]=cvt_tf32(wpre[j].w);
        }
        __syncthreads();
        if (k0 + 32 < K){
            #pragma unroll
            for (int j=0;j<4;j++){
                apre[j] = *(const float4*)&A[(row0+ar)*K + k0+32 + ah + j*4];
                wpre[j] = *(const float4*)&W[(k0+32+br)*N + n0 + bc + j*4];
            }
        }
        #pragma unroll
        for (int ks=0; ks<4; ks++){
            unsigned a[2][4];
            #pragma unroll
            for (int mf=0; mf<2; mf++){
                int rowb = wm*32 + mf*16 + tq;
                uint2 x = *(uint2*)&As[rowb*40 + ks*8 + 2*te];
                uint2 y = *(uint2*)&As[(rowb+8)*40 + ks*8 + 2*te];
                a[mf][0]=x.x; a[mf][1]=y.x; a[mf][2]=x.y; a[mf][3]=y.y;
            }
            #pragma unroll
            for (int nf=0; nf<8; nf++){
                int col = wn*64 + nf*8 + tq;
                unsigned b0 = Bs[(ks*8+te)*136 + col];
                unsigned b1 = Bs[(ks*8+te+4)*136 + col];
                mma_tf32(acc[0][nf], a[0][0],a[0][1],a[0][2],a[0][3], b0,b1);
                mma_tf32(acc[1][nf], a[1][0],a[1][1],a[1][2],a[1][3], b0,b1);
            }
        }
        __syncthreads();
    }
    #pragma unroll
    for (int mf=0; mf<2; mf++){
        int row = row0 + wm*32 + mf*16 + tq;
        #pragma unroll
        for (int nf=0; nf<8; nf++){
            int col = n0 + wn*64 + nf*8 + 2*te;
            float bv0 = bias[col], bv1 = bias[col+1];
            *(float2*)&C[(size_t)row*N + col] =
                make_float2(acc[mf][nf][0]+bv0, acc[mf][nf][1]+bv1);
            *(float2*)&C[(size_t)(row+8)*N + col] =
                make_float2(acc[mf][nf][2]+bv0, acc[mf][nf][3]+bv1);
        }
    }
}

// -------- reorg (+ optional LN): tmp[rb][e] -> out[b][h][r][d], warp/row ----
__global__ __launch_bounds__(256) void reorg_kernel(const float* __restrict__ tmp,
        float* __restrict__ out, const float* __restrict__ gg,
        const float* __restrict__ bb, int mode){
    int wid  = blockIdx.x*8 + (threadIdx.x >> 5);
    int lane = threadIdx.x & 31;
    int rb = wid >> 4, h = wid & 15;
    const float* src = tmp + rb*E_ + h*64;
    float v0 = src[lane], v1 = src[32+lane];
    int b = rb & 1, r = rb >> 1;
    float* dst = out + (((b*H_ + h)*R_) + r)*64;
    if (mode == 0){
        dst[lane] = v0*SCALE_; dst[32+lane] = v1*SCALE_;
        return;
    }
    float s = v0 + v1;
    #pragma unroll
    for (int o=16;o;o>>=1) s += __shfl_xor_sync(0xffffffffu, s, o);
    float mean = s*(1.f/64.f);
    float d0 = v0-mean, d1 = v1-mean;
    float vv = d0*d0 + d1*d1;
    #pragma unroll
    for (int o=16;o;o>>=1) vv += __shfl_xor_sync(0xffffffffu, vv, o);
    float scl = rsqrtf(vv*(1.f/64.f) + 1e-5f);
    dst[lane]    = d0*scl*gg[lane]    + bb[lane];
    dst[32+lane] = d1*scl*gg[32+lane] + bb[32+lane];
}

// -------- r0[h][z][d] = sum_c rel_emb0[z][c] * Wr0[c][h*64+d] + br0 ---------
__global__ __launch_bounds__(64) void r0_kernel(const float* __restrict__ rel_emb0,
        const float* __restrict__ Wr0, const float* __restrict__ br0){
    int z = blockIdx.x >> 4, h = blockIdx.x & 15;
    int d = threadIdx.x;
    float a = br0[h*64+d];
    #pragma unroll 8
    for (int c=0;c<64;c++) a += rel_emb0[z*64+c]*Wr0[c*E_ + h*64 + d];
    g_r0[(h*Z_ + z)*64 + d] = a;
}

// ---------------- attention smem layout (floats) ---------------------------
// Q[64][68] perm | K[64][68] perm | V[64][72] | P[64][68] perm | QR[64][68] | idx[64][64]
#define AQ  0
#define AK  4352
#define AV  8704
#define ASP 13312
#define AQR 17664
#define AIX 22016
#define ATTN_SMEM_F 26112
#define ATTN_SMEM_BYTES (ATTN_SMEM_F*4)

// stage 64x64 tile, tf32-converted, column-permuted, dst stride 68
__device__ __forceinline__ void stage_perm(unsigned* dst, const float* src,
        int lrow, int half){
    const float4* p = (const float4*)(src + lrow*64 + half);
    unsigned* d = dst + lrow*68;
    #pragma unroll
    for (int j=0;j<8;j++){
        float4 v = p[j];
        int c = half + j*4;
        int base = (c & ~7) + ((c>>2)&1);
        d[base+0]=cvt_tf32(v.x); d[base+2]=cvt_tf32(v.y);
        d[base+4]=cvt_tf32(v.z); d[base+6]=cvt_tf32(v.w);
    }
}
// stage V 64x64 tile, tf32, normal layout, stride 72
__device__ __forceinline__ void stage_v(unsigned* dst, const float* src,
        int lrow, int half){
    const float4* p = (const float4*)(src + lrow*64 + half);
    uint4* d = (uint4*)(dst + lrow*72 + half);
    #pragma unroll
    for (int j=0;j<8;j++){
        float4 v = p[j];
        uint4 u; u.x=cvt_tf32(v.x); u.y=cvt_tf32(v.y);
        u.z=cvt_tf32(v.z); u.w=cvt_tf32(v.w);
        d[j] = u;
    }
}
__device__ __forceinline__ void stage_idx(int* dst, const int* src,
        int lrow, int half){
    const int4* p = (const int4*)(src + (size_t)lrow*R_ + half);
    int4* d = (int4*)(dst + lrow*64 + half);
    #pragma unroll
    for (int j=0;j<8;j++) d[j] = p[j];
}

// score/QR mma: S[8][4] += Qsm(rows w*16..) x Ksm(all 64)^T
#define SCORE_MMA(SREG, QOFF, KOFF)                                          \
    {                                                                        \
        _Pragma("unroll")                                                    \
        for (int ks=0; ks<8; ks++){                                          \
            uint2 x = *(uint2*)&smu[(QOFF) + (w*16+tq)*68 + ks*8 + 2*te];    \
            uint2 y = *(uint2*)&smu[(QOFF) + (w*16+tq+8)*68 + ks*8 + 2*te];  \
            _Pragma("unroll")                                                \
            for (int nf=0; nf<8; nf++){                                      \
                uint2 bb = *(uint2*)&smu[(KOFF) + (nf*8+tq)*68 + ks*8 + 2*te];\
                mma_tf32(SREG[nf], x.x, y.x, x.y, y.y, bb.x, bb.y);          \
            }                                                                \
        }                                                                    \
    }

// softmax on register scores + P spill + PV accumulate
#define SOFTMAX_PV(USE_BIAS)                                                 \
    {                                                                        \
        if (USE_BIAS){                                                       \
            const int* ix = (const int*)(sm + AIX);                          \
            _Pragma("unroll")                                                \
            for (int nf=0; nf<8; nf++){                                      \
                int c = nf*8 + 2*te;                                         \
                int2 i0 = *(const int2*)&ix[(w*16+tq)*64 + c];               \
                int2 i1 = *(const int2*)&ix[(w*16+tq+8)*64 + c];             \
                S[nf][0] += sm[AQR + (w*16+tq)*68 + i0.x];                   \
                S[nf][1] += sm[AQR + (w*16+tq)*68 + i0.y];                   \
                S[nf][2] += sm[AQR + (w*16+tq+8)*68 + i1.x];                 \
                S[nf][3] += sm[AQR + (w*16+tq+8)*68 + i1.y];                 \
            }                                                                \
        }                                                                    \
        float tm0 = -1e30f, tm1 = -1e30f;                                    \
        _Pragma("unroll")                                                    \
        for (int nf=0; nf<8; nf++){                                          \
            tm0 = fmaxf(tm0, fmaxf(S[nf][0], S[nf][1]));                     \
            tm1 = fmaxf(tm1, fmaxf(S[nf][2], S[nf][3]));                     \
        }                                                                    \
        tm0 = fmaxf(tm0, __shfl_xor_sync(0xffffffffu, tm0, 1));              \
        tm0 = fmaxf(tm0, __shfl_xor_sync(0xffffffffu, tm0, 2));              \
        tm1 = fmaxf(tm1, __shfl_xor_sync(0xffffffffu, tm1, 1));              \
        tm1 = fmaxf(tm1, __shfl_xor_sync(0xffffffffu, tm1, 2));              \
        float mn0 = fmaxf(mr0, tm0), mn1 = fmaxf(mr1, tm1);                  \
        float f0 = __expf(mr0 - mn0), f1 = __expf(mr1 - mn1);                \
        mr0 = mn0; mr1 = mn1;                                                \
        float rs0 = 0.f, rs1 = 0.f;                                          \
        _Pragma("unroll")                                                    \
        for (int nf=0; nf<8; nf++){                                          \
            S[nf][0] = __expf(S[nf][0]-mn0); rs0 += S[nf][0];                \
            S[nf][1] = __expf(S[nf][1]-mn0); rs0 += S[nf][1];                \
            S[nf][2] = __expf(S[nf][2]-mn1); rs1 += S[nf][2];                \
            S[nf][3] = __expf(S[nf][3]-mn1); rs1 += S[nf][3];                \
        }                                                                    \
        rs0 += __shfl_xor_sync(0xffffffffu, rs0, 1);                         \
        rs0 += __shfl_xor_sync(0xffffffffu, rs0, 2);                         \
        rs1 += __shfl_xor_sync(0xffffffffu, rs1, 1);                         \
        rs1 += __shfl_xor_sync(0xffffffffu, rs1, 2);                         \
        lr0 = lr0*f0 + rs0; lr1 = lr1*f1 + rs1;                              \
        _Pragma("unroll")                                                    \
        for (int nf=0; nf<8; nf++){                                          \
            O[nf][0]*=f0; O[nf][1]*=f0; O[nf][2]*=f1; O[nf][3]*=f1;          \
        }                                                                    \
        _Pragma("unroll")                                                    \
        for (int nf=0; nf<8; nf++){                                          \
            int c0 = nf*8 + 2*te, c1 = c0+1;                                 \
            int p0 = (c0 & ~7) + 2*(c0&3) + ((c0>>2)&1);                     \
            int p1 = (c1 & ~7) + 2*(c1&3) + ((c1>>2)&1);                     \
            smu[ASP + (w*16+tq)*68 + p0]   = cvt_tf32(S[nf][0]);             \
            smu[ASP + (w*16+tq)*68 + p1]   = cvt_tf32(S[nf][1]);             \
            smu[ASP + (w*16+tq+8)*68 + p0] = cvt_tf32(S[nf][2]);             \
            smu[ASP + (w*16+tq+8)*68 + p1] = cvt_tf32(S[nf][3]);             \
        }                                                                    \
        __syncwarp();                                                        \
        _Pragma("unroll")                                                    \
        for (int ks=0; ks<8; ks++){                                          \
            uint2 x = *(uint2*)&smu[ASP + (w*16+tq)*68 + ks*8 + 2*te];       \
            uint2 y = *(uint2*)&smu[ASP + (w*16+tq+8)*68 + ks*8 + 2*te];     \
            _Pragma("unroll")                                                \
            for (int nf=0; nf<8; nf++){                                      \
                unsigned b0 = smu[AV + (ks*8+te)*72 + nf*8 + tq];            \
                unsigned b1 = smu[AV + (ks*8+te+4)*72 + nf*8 + tq];          \
                mma_tf32(O[nf], x.x, y.x, x.y, y.y, b0, b1);                 \
            }                                                                \
        }                                                                    \
    }

// -------------------- fused main attention ---------------------------------
// grid (R/64, H, B), 128 threads (4 warps x 16 query rows each).
__global__ __launch_bounds__(128,2) void attn_main_kernel(const int* __restrict__ rel_idx){
    extern __shared__ float sm[];
    unsigned* smu = (unsigned*)sm;
    int t = threadIdx.x, lane = t & 31, w = t >> 5;
    int tq = lane >> 2, te = lane & 3;
    int b = blockIdx.z, h = blockIdx.y, bh = b*H_ + h;
    int q0 = blockIdx.x * 64;
    int lrow = t >> 1, half = (t & 1) * 32;

    stage_perm(smu + AQ, g_q + ((size_t)bh*R_ + q0)*64, lrow, half);
    stage_perm(smu + AK, g_r0 + h*Z_*64, lrow, half);
    __syncthreads();

    float S[8][4];
    #pragma unroll
    for (int nf=0;nf<8;nf++){ S[nf][0]=S[nf][1]=S[nf][2]=S[nf][3]=0.f; }
    SCORE_MMA(S, AQ, AK);
    #pragma unroll
    for (int nf=0; nf<8; nf++){
        *(float2*)&sm[AQR + (w*16+tq)*68 + nf*8 + 2*te] =
            make_float2(S[nf][0], S[nf][1]);
        *(float2*)&sm[AQR + (w*16+tq+8)*68 + nf*8 + 2*te] =
            make_float2(S[nf][2], S[nf][3]);
    }

    float O[8][4];
    #pragma unroll
    for (int nf=0;nf<8;nf++){ O[nf][0]=O[nf][1]=O[nf][2]=O[nf][3]=0.f; }
    float mr0 = -1e30f, mr1 = -1e30f, lr0 = 0.f, lr1 = 0.f;

    for (int kt = 0; kt < 33; kt++){
        __syncthreads();
        if (kt == 0){
            stage_perm(smu + AK, g_k2 + (size_t)bh*S_*64, lrow, half);
            stage_v(smu + AV, g_v2 + (size_t)bh*S_*64, lrow, half);
        } else {
            int k0 = (kt-1)*64;
            stage_perm(smu + AK, g_k + ((size_t)bh*R_ + k0)*64, lrow, half);
            stage_v(smu + AV, g_v + ((size_t)bh*R_ + k0)*64, lrow, half);
            stage_idx((int*)(sm + AIX),
                rel_idx + (size_t)(b*(S_+R_) + S_ + q0 + lrow)*R_ + k0 - (size_t)lrow*R_,
                lrow, half);
        }
        __syncthreads();
        #pragma unroll
        for (int nf=0;nf<8;nf++){ S[nf][0]=S[nf][1]=S[nf][2]=S[nf][3]=0.f; }
        SCORE_MMA(S, AQ, AK);
        if (kt == 0){ SOFTMAX_PV(0); } else { SOFTMAX_PV(1); }
    }

    float inv0 = 1.f/lr0, inv1 = 1.f/lr1;
    int qa = q0 + w*16 + tq;
    #pragma unroll
    for (int nf=0; nf<8; nf++){
        int c = nf*8 + 2*te;
        *(float2*)&g_attn[((size_t)qa*B_ + b)*E_ + h*64 + c] =
            make_float2(O[nf][0]*inv0, O[nf][1]*inv0);
        *(float2*)&g_attn[((size_t)(qa+8)*B_ + b)*E_ + h*64 + c] =
            make_float2(O[nf][2]*inv1, O[nf][3]*inv1);
    }
}

// -------------------- fused sum attention (split-K) -------------------------
// grid (B*H, SPLITS), 128 threads; each split covers 256 keys (4 tiles).
__global__ __launch_bounds__(128,2) void attn_sum_kernel(const int* __restrict__ tok,
        const float* __restrict__ emb_sum, const int* __restrict__ rel_idx){
    extern __shared__ float sm[];
    unsigned* smu = (unsigned*)sm;
    int t = threadIdx.x, lane = t & 31, w = t >> 5;
    int tq = lane >> 2, te = lane & 3;
    int bh = blockIdx.x, split = blockIdx.y;
    int b = bh >> 4, h = bh & 15;
    int lrow = t >> 1, half = (t & 1) * 32;

    {   // gather + scale sum_q, permuted tf32
        int token = tok[b*S_ + lrow];
        const float4* p = (const float4*)(emb_sum + (size_t)token*E_ + h*64 + half);
        unsigned* d = smu + AQ + lrow*68;
        #pragma unroll
        for (int j=0;j<8;j++){
            float4 v = p[j];
            int c = half + j*4;
            int base = (c & ~7) + ((c>>2)&1);
            d[base+0]=cvt_tf32(v.x*SCALE_); d[base+2]=cvt_tf32(v.y*SCALE_);
            d[base+4]=cvt_tf32(v.z*SCALE_); d[base+6]=cvt_tf32(v.w*SCALE_);
        }
    }
    stage_perm(smu + AK, g_r0 + h*Z_*64, lrow, half);
    __syncthreads();

    float S[8][4];
    #pragma unroll
    for (int nf=0;nf<8;nf++){ S[nf][0]=S[nf][1]=S[nf][2]=S[nf][3]=0.f; }
    SCORE_MMA(S, AQ, AK);
    #pragma unroll
    for (int nf=0; nf<8; nf++){
        *(float2*)&sm[AQR + (w*16+tq)*68 + nf*8 + 2*te] =
            make_float2(S[nf][0], S[nf][1]);
        *(float2*)&sm[AQR + (w*16+tq+8)*68 + nf*8 + 2*te] =
            make_float2(S[nf][2], S[nf][3]);
    }

    float O[8][4];
    #pragma unroll
    for (int nf=0;nf<8;nf++){ O[nf][0]=O[nf][1]=O[nf][2]=O[nf][3]=0.f; }
    float mr0 = -1e30f, mr1 = -1e30f, lr0 = 0.f, lr1 = 0.f;

    for (int kt = 0; kt < 4; kt++){
        __syncthreads();
        int k0 = split*256 + kt*64;
        stage_perm(smu + AK, g_k + ((size_t)bh*R_ + k0)*64, lrow, half);
        stage_v(smu + AV, g_v + ((size_t)bh*R_ + k0)*64, lrow, half);
        stage_idx((int*)(sm + AIX),
            rel_idx + (size_t)(b*(S_+R_))*R_ + k0, lrow, half);
        __syncthreads();
        #pragma unroll
        for (int nf=0;nf<8;nf++){ S[nf][0]=S[nf][1]=S[nf][2]=S[nf][3]=0.f; }
        SCORE_MMA(S, AQ, AK);
        SOFTMAX_PV(1);
    }

    int pb = bh*SPLITS + split;
    int s0 = w*16 + tq;
    #pragma unroll
    for (int nf=0; nf<8; nf++){
        int c = nf*8 + 2*te;
        *(float2*)&g_pacc[((size_t)pb*S_ + s0)*64 + c] =
            make_float2(O[nf][0], O[nf][1]);
        *(float2*)&g_pacc[((size_t)pb*S_ + s0 + 8)*64 + c] =
            make_float2(O[nf][2], O[nf][3]);
    }
    if (te == 0 && (lane & 3) == 0){
        g_pm[pb*S_ + s0] = mr0;    g_pm[pb*S_ + s0 + 8] = mr1;
        g_pl[pb*S_ + s0] = lr0;    g_pl[pb*S_ + s0 + 8] = lr1;
    }
}

// -------- combine split-K partials -> g_sumx2 -------------------------------
__global__ __launch_bounds__(64) void combine_kernel(){
    int rowq = blockIdx.x;            // bh*64 + s
    int bh = rowq >> 6, s = rowq & 63;
    int d = threadIdx.x;
    float mv[SPLITS];
    float M = -1e30f;
    #pragma unroll
    for (int i=0;i<SPLITS;i++){
        mv[i] = g_pm[(bh*SPLITS + i)*S_ + s];
        M = fmaxf(M, mv[i]);
    }
    float L = 0.f, acc = 0.f;
    #pragma unroll
    for (int i=0;i<SPLITS;i++){
        float w = __expf(mv[i] - M);
        acc += w * g_pacc[((size_t)(bh*SPLITS + i)*S_ + s)*64 + d];
        L   += w * g_pl[(bh*SPLITS + i)*S_ + s];
    }
    g_sumx2[(bh*S_ + s)*64 + d] = acc / L;
}

// -------- per-row (b,h,s) projections sum_k2/sum_v2 with LN ----------------
__global__ __launch_bounds__(64) void k2v2_kernel(const float* __restrict__ Wk2,
        const float* __restrict__ bk2, const float* __restrict__ Wv2,
        const float* __restrict__ bv2, const float* __restrict__ g1,
        const float* __restrict__ b1, const float* __restrict__ g2,
        const float* __restrict__ b2){
    __shared__ float xr[64];
    __shared__ float red[2];
    int row = blockIdx.x, t = threadIdx.x;
    xr[t] = g_sumx2[row*64 + t];
    __syncthreads();
    #pragma unroll
    for (int pass=0; pass<2; pass++){
        const float* W  = pass ? Wv2 : Wk2;
        const float* bb = pass ? bv2 : bk2;
        const float* gg = pass ? g2  : g1;
        const float* bt = pass ? b2  : b1;
        float* outp     = pass ? g_v2 : g_k2;
        float a = bb[t];
        #pragma unroll 8
        for (int j=0;j<64;j++) a += xr[j]*W[j*64+t];
        float s = a;
        #pragma unroll
        for (int o=16;o;o>>=1) s += __shfl_xor_sync(0xffffffffu, s, o);
        if ((t&31)==0) red[t>>5] = s;
        __syncthreads();
        float mean = (red[0]+red[1]) * (1.f/64.f);
        __syncthreads();
        float dv = a - mean;
        float v2 = dv*dv;
        #pragma unroll
        for (int o=16;o;o>>=1) v2 += __shfl_xor_sync(0xffffffffu, v2, o);
        if ((t&31)==0) red[t>>5] = v2;
        __syncthreads();
        float var = (red[0]+red[1]) * (1.f/64.f);
        __syncthreads();
        outp[row*64 + t] = dv*rsqrtf(var+1e-5f)*gg[t] + bt[t];
    }
}

// ---------------------------------------------------------------------------
extern "C" void kernel_launch(void* const* d_in, const int* in_sizes, int n_in,
                              void* d_out, int out_size){
    const float* reg_x   = (const float*)d_in[0];
    const int*   tok     = (const int*)d_in[1];
    const int*   rel_idx = (const int*)d_in[2];
    const float* emb_sum  = (const float*)d_in[5];
    const float* rel_emb0 = (const float*)d_in[6];
    const float* Wq  = (const float*)d_in[7];  const float* bq  = (const float*)d_in[8];
    const float* Wk  = (const float*)d_in[9];  const float* bk  = (const float*)d_in[10];
    const float* Wv  = (const float*)d_in[11]; const float* bv  = (const float*)d_in[12];
    const float* Wr0 = (const float*)d_in[13]; const float* br0 = (const float*)d_in[14];
    const float* Wk2 = (const float*)d_in[15]; const float* bk2 = (const float*)d_in[16];
    const float* Wv2 = (const float*)d_in[17]; const float* bv2 = (const float*)d_in[18];
    const float* Wo  = (const float*)d_in[19]; const float* bo  = (const float*)d_in[20];
    const float* lnkg  = (const float*)d_in[21]; const float* lnkb  = (const float*)d_in[22];
    const float* lnvg  = (const float*)d_in[23]; const float* lnvb  = (const float*)d_in[24];
    const float* lnk2g = (const float*)d_in[25]; const float* lnk2b = (const float*)d_in[26];
    const float* lnv2g = (const float*)d_in[27]; const float* lnv2b = (const float*)d_in[28];
    float* out = (float*)d_out;

    cudaFuncSetAttribute(attn_sum_kernel,  cudaFuncAttributeMaxDynamicSharedMemorySize, ATTN_SMEM_BYTES);
    cudaFuncSetAttribute(attn_main_kernel, cudaFuncAttributeMaxDynamicSharedMemorySize, ATTN_SMEM_BYTES);

    float *tq, *tk, *tv, *gq, *gk, *gv, *gattn;
    cudaGetSymbolAddress((void**)&tq, g_tmp_q);
    cudaGetSymbolAddress((void**)&tk, g_tmp_k);
    cudaGetSymbolAddress((void**)&tv, g_tmp_v);
    cudaGetSymbolAddress((void**)&gq, g_q);
    cudaGetSymbolAddress((void**)&gk, g_k);
    cudaGetSymbolAddress((void**)&gv, g_v);
    cudaGetSymbolAddress((void**)&gattn, g_attn);

    dim3 ggrid(E_/128, MROWS/128);   // (8, 32)
    gemm_bias<<<ggrid, 256>>>(reg_x, Wq, bq, tq);
    gemm_bias<<<ggrid, 256>>>(reg_x, Wk, bk, tk);
    gemm_bias<<<ggrid, 256>>>(reg_x, Wv, bv, tv);

    reorg_kernel<<<MROWS*H_/8, 256>>>(tq, gq, (const float*)0, (const float*)0, 0);
    reorg_kernel<<<MROWS*H_/8, 256>>>(tk, gk, lnkg, lnkb, 1);
    reorg_kernel<<<MROWS*H_/8, 256>>>(tv, gv, lnvg, lnvb, 1);

    r0_kernel<<<Z_*H_, 64>>>(rel_emb0, Wr0, br0);

    attn_sum_kernel<<<dim3(B_*H_, SPLITS), 128, ATTN_SMEM_BYTES>>>(tok, emb_sum, rel_idx);
    combine_kernel<<<B_*H_*S_, 64>>>();
    k2v2_kernel<<<B_*H_*S_, 64>>>(Wk2, bk2, Wv2, bv2, lnk2g, lnk2b, lnv2g, lnv2b);

    attn_main_kernel<<<dim3(R_/64, H_, B_), 128, ATTN_SMEM_BYTES>>>(rel_idx);

    gemm_bias<<<ggrid, 256>>>(gattn, Wo, bo, out);
}

// round 4
// speedup vs baseline: 6.0897x; 1.5984x over previous
#include <cuda_runtime.h>
#include <math.h>

#define H_ 16
#define D_ 64
#define R_ 2048
#define S_ 64
#define B_ 2
#define E_ 1024
#define Z_ 64
#define SCALE_ 0.125f
#define MROWS (R_*B_)   /* 4096 */
#define SPLITS 8
#define TOTLEN (S_+R_)  /* 2112 */

// ---------------- scratch (device globals: allocation-free) ----------------
__device__ float g_tmp_q[MROWS*E_];
__device__ float g_tmp_k[MROWS*E_];
__device__ float g_tmp_v[MROWS*E_];
__device__ unsigned g_qp[B_*H_*R_*D_];    // Q tf32, [bh][r][d-perm], scaled
__device__ unsigned g_kp[B_*H_*R_*D_];    // K tf32, [bh][r][d-perm]
__device__ unsigned g_vt[B_*H_*D_*R_];    // V tf32, [bh][d][r-perm]
__device__ unsigned g_r0p[H_*Z_*D_];      // r0 tf32, [h][z][d-perm]
__device__ unsigned g_k2p[B_*H_*S_*D_];   // k2 tf32, [bh][s][d-perm]
__device__ unsigned g_v2t[B_*H_*D_*S_];   // v2 tf32, [bh][d][s-perm]
__device__ unsigned char g_idx8[B_*TOTLEN*R_];
__device__ float g_sumx2[B_*H_*S_*D_];
__device__ float g_attn[MROWS*E_];
__device__ float g_pacc[B_*H_*SPLITS*S_*D_];
__device__ float g_pm[B_*H_*SPLITS*S_];
__device__ float g_pl[B_*H_*SPLITS*S_];

#define PERM8(c) ((((c)) & ~7) + 2*((c)&3) + (((c)>>2)&1))

// ---------------- tf32 / async helpers -------------------------------------
__device__ __forceinline__ unsigned cvt_tf32(float x){
    unsigned u; asm("cvt.rna.tf32.f32 %0, %1;" : "=r"(u) : "f"(x)); return u;
}
__device__ __forceinline__ void mma_tf32(float* c,
        unsigned a0, unsigned a1, unsigned a2, unsigned a3,
        unsigned b0, unsigned b1){
    asm volatile(
        "mma.sync.aligned.m16n8k8.row.col.f32.tf32.tf32.f32 "
        "{%0,%1,%2,%3},{%4,%5,%6,%7},{%8,%9},{%0,%1,%2,%3};"
        : "+f"(c[0]), "+f"(c[1]), "+f"(c[2]), "+f"(c[3])
        : "r"(a0), "r"(a1), "r"(a2), "r"(a3), "r"(b0), "r"(b1));
}
__device__ __forceinline__ void cp16(void* dst, const void* src){
    unsigned d = (unsigned)__cvta_generic_to_shared(dst);
    asm volatile("cp.async.cg.shared.global [%0],[%1],16;" :: "r"(d), "l"(src));
}
#define CP_COMMIT() asm volatile("cp.async.commit_group;" ::: "memory")
#define CP_WAIT0()  asm volatile("cp.async.wait_group 0;" ::: "memory")
#define CP_WAIT1()  asm volatile("cp.async.wait_group 1;" ::: "memory")

// ---------------- tf32 tensor-core GEMM ------------------------------------
// C[M,N] = A[M,1024] @ W[1024,N] + bias. Block 128x128, 256 thr, 8 warps.
__global__ __launch_bounds__(256) void gemm_bias(const float* __restrict__ A,
        const float* __restrict__ W, const float* __restrict__ bias,
        float* __restrict__ C){
    const int K = 1024, N = 1024;
    __shared__ unsigned As[128*36];     // [row][k-permuted], stride 36 (bank-clean)
    __shared__ unsigned Bs[32*136];     // [k][n], stride 136
    int t = threadIdx.x, lane = t & 31, w = t >> 5;
    int wm = w >> 1, wn = w & 1;
    int tq = lane >> 2, te = lane & 3;
    int row0 = blockIdx.y * 128, n0 = blockIdx.x * 128;
    int ar = t >> 1, ah = (t & 1) * 16;
    int br = t >> 3, bc = (t & 7) * 16;

    float acc[2][8][4];
    #pragma unroll
    for (int m=0;m<2;m++)
        #pragma unroll
        for (int n=0;n<8;n++)
            #pragma unroll
            for (int j=0;j<4;j++) acc[m][n][j]=0.f;

    float4 apre[4], wpre[4];
    #pragma unroll
    for (int j=0;j<4;j++){
        apre[j] = *(const float4*)&A[(row0+ar)*K + ah + j*4];
        wpre[j] = *(const float4*)&W[br*N + n0 + bc + j*4];
    }

    for (int k0 = 0; k0 < K; k0 += 32){
        #pragma unroll
        for (int j=0;j<4;j++){
            int c = ah + j*4;
            int base = ar*36 + (c & ~7) + ((c>>2)&1);
            As[base+0]=cvt_tf32(apre[j].x); As[base+2]=cvt_tf32(apre[j].y);
            As[base+4]=cvt_tf32(apre[j].z); As[base+6]=cvt_tf32(apre[j].w);
            unsigned* bd = &Bs[br*136 + bc + j*4];
            bd[0]=cvt_tf32(wpre[j].x); bd[1]=cvt_tf32(wpre[j].y);
            bd[2]=cvt_tf32(wpre[j].z); bd[3]=cvt_tf32(wpre[j].w);
        }
        __syncthreads();
        if (k0 + 32 < K){
            #pragma unroll
            for (int j=0;j<4;j++){
                apre[j] = *(const float4*)&A[(row0+ar)*K + k0+32 + ah + j*4];
                wpre[j] = *(const float4*)&W[(k0+32+br)*N + n0 + bc + j*4];
            }
        }
        #pragma unroll
        for (int ks=0; ks<4; ks++){
            unsigned a[2][4];
            #pragma unroll
            for (int mf=0; mf<2; mf++){
                int rowb = wm*32 + mf*16 + tq;
                uint2 x = *(uint2*)&As[rowb*36 + ks*8 + 2*te];
                uint2 y = *(uint2*)&As[(rowb+8)*36 + ks*8 + 2*te];
                a[mf][0]=x.x; a[mf][1]=y.x; a[mf][2]=x.y; a[mf][3]=y.y;
            }
            #pragma unroll
            for (int nf=0; nf<8; nf++){
                int col = wn*64 + nf*8 + tq;
                unsigned b0 = Bs[(ks*8+te)*136 + col];
                unsigned b1 = Bs[(ks*8+te+4)*136 + col];
                mma_tf32(acc[0][nf], a[0][0],a[0][1],a[0][2],a[0][3], b0,b1);
                mma_tf32(acc[1][nf], a[1][0],a[1][1],a[1][2],a[1][3], b0,b1);
            }
        }
        __syncthreads();
    }
    #pragma unroll
    for (int mf=0; mf<2; mf++){
        int row = row0 + wm*32 + mf*16 + tq;
        #pragma unroll
        for (int nf=0; nf<8; nf++){
            int col = n0 + wn*64 + nf*8 + 2*te;
            float bv0 = bias[col], bv1 = bias[col+1];
            *(float2*)&C[(size_t)row*N + col] =
                make_float2(acc[mf][nf][0]+bv0, acc[mf][nf][1]+bv1);
            *(float2*)&C[(size_t)(row+8)*N + col] =
                make_float2(acc[mf][nf][2]+bv0, acc[mf][nf][3]+bv1);
        }
    }
}

// -------- reorg: tmp[rb][e] -> attention layouts (tf32), warp per (rb,h) ----
// mode 0: Q scaled -> g_qp perm; mode 1: LN -> g_kp perm; mode 2: LN -> g_vt transposed
__global__ __launch_bounds__(256) void reorg_kernel(const float* __restrict__ tmp,
        const float* __restrict__ gg, const float* __restrict__ bb, int mode){
    int wid  = blockIdx.x*8 + (threadIdx.x >> 5);
    int lane = threadIdx.x & 31;
    int rb = wid >> 4, h = wid & 15;
    const float* src = tmp + rb*E_ + h*64;
    float v0 = src[lane], v1 = src[32+lane];
    int b = rb & 1, r = rb >> 1;
    int bh = b*H_ + h;
    if (mode == 0){
        unsigned* dst = g_qp + ((size_t)bh*R_ + r)*64;
        dst[PERM8(lane)]    = cvt_tf32(v0*SCALE_);
        dst[PERM8(lane+32)] = cvt_tf32(v1*SCALE_);
        return;
    }
    float s = v0 + v1;
    #pragma unroll
    for (int o=16;o;o>>=1) s += __shfl_xor_sync(0xffffffffu, s, o);
    float mean = s*(1.f/64.f);
    float d0 = v0-mean, d1 = v1-mean;
    float vv = d0*d0 + d1*d1;
    #pragma unroll
    for (int o=16;o;o>>=1) vv += __shfl_xor_sync(0xffffffffu, vv, o);
    float scl = rsqrtf(vv*(1.f/64.f) + 1e-5f);
    float o0 = d0*scl*gg[lane]    + bb[lane];
    float o1 = d1*scl*gg[32+lane] + bb[32+lane];
    if (mode == 1){
        unsigned* dst = g_kp + ((size_t)bh*R_ + r)*64;
        dst[PERM8(lane)]    = cvt_tf32(o0);
        dst[PERM8(lane+32)] = cvt_tf32(o1);
    } else {
        int rp = PERM8(r);
        g_vt[((size_t)bh*64 + lane)*R_ + rp]    = cvt_tf32(o0);
        g_vt[((size_t)bh*64 + lane+32)*R_ + rp] = cvt_tf32(o1);
    }
}

// -------- r0p[h][z][dperm] = tf32( rel_emb0@Wr0 + br0 ) ---------------------
__global__ __launch_bounds__(64) void r0_kernel(const float* __restrict__ rel_emb0,
        const float* __restrict__ Wr0, const float* __restrict__ br0){
    int z = blockIdx.x >> 4, h = blockIdx.x & 15;
    int d = threadIdx.x;
    float a = br0[h*64+d];
    #pragma unroll 8
    for (int c=0;c<64;c++) a += rel_emb0[z*64+c]*Wr0[c*E_ + h*64 + d];
    g_r0p[(h*Z_ + z)*64 + PERM8(d)] = cvt_tf32(a);
}

// -------- compress rel_idx (int32 < 64) to u8 -------------------------------
__global__ __launch_bounds__(256) void idx8_kernel(const int* __restrict__ rel){
    size_t i = (size_t)blockIdx.x*256 + threadIdx.x;   // each handles 4 ints
    int4 v = ((const int4*)rel)[i];
    uchar4 u; u.x=(unsigned char)v.x; u.y=(unsigned char)v.y;
    u.z=(unsigned char)v.z; u.w=(unsigned char)v.w;
    ((uchar4*)g_idx8)[i] = u;
}

// ---------------- attention smem layout (floats) ---------------------------
#define KB(b)  ((b)*4352)            /* K tile [64 keys][68], tf32 perm */
#define VB(b)  (8704 + (b)*4352)     /* Vt tile [64 d][68], tf32 key-perm */
#define IXF(b) (17408 + (b)*1280)    /* idx u8 [64 q][80 bytes] */
#define AQR    19968                 /* qr fp32 [64 q][68] plain cols */
#define APS    24320                 /* P tf32 [64 q][68] perm cols */
#define ATTN_SMEM_F 28672
#define ATTN_SMEM_BYTES (ATTN_SMEM_F*4)   /* 114688 */

__device__ __forceinline__ void stage_kv(float* sm, int kbo, int vbo,
        const unsigned* kg, const unsigned* vg, long vstride, int t){
    #pragma unroll
    for (int j=0;j<8;j++){
        int c = t + 128*j;
        cp16(&sm[kbo + (c>>4)*68 + (c&15)*4], kg + c*4);
        cp16(&sm[vbo + (c>>4)*68 + (c&15)*4], vg + (long)(c>>4)*vstride + (c&15)*4);
    }
}
__device__ __forceinline__ void stage_ix(char* smc, int ixbyte,
        const unsigned char* ig, int t){
    #pragma unroll
    for (int j=0;j<2;j++){
        int c = t + 128*j;
        cp16(smc + ixbyte + (c>>2)*80 + (c&3)*16, ig + (size_t)(c>>2)*R_ + (c&3)*16);
    }
}

// SCORE: S[8][4] += Qregs x Ktile^T
#define SCORE_MMA(SREG, KOFF)                                                \
    {                                                                        \
        _Pragma("unroll")                                                    \
        for (int ks=0; ks<8; ks++){                                          \
            _Pragma("unroll")                                                \
            for (int nf=0; nf<8; nf++){                                      \
                uint2 bb = *(uint2*)&smu[(KOFF) + (nf*8+tq)*68 + ks*8 + 2*te];\
                mma_tf32(SREG[nf], qa[ks][0],qa[ks][1],qa[ks][2],qa[ks][3],  \
                         bb.x, bb.y);                                        \
            }                                                                \
        }                                                                    \
    }

// softmax (register state) + P spill + PV accumulate from Vt tile
#define SOFTMAX_PV(USE_BIAS, IXBYTE, VOFF)                                   \
    {                                                                        \
        if (USE_BIAS){                                                       \
            const unsigned char* ixb = (const unsigned char*)smc + (IXBYTE); \
            _Pragma("unroll")                                                \
            for (int nf=0; nf<8; nf++){                                      \
                unsigned v0 = *(const unsigned short*)                       \
                    (ixb + (w*16+tq)*80 + nf*8 + 2*te);                      \
                unsigned v1 = *(const unsigned short*)                       \
                    (ixb + (w*16+tq+8)*80 + nf*8 + 2*te);                    \
                S[nf][0] += sm[AQR + (w*16+tq)*68 + (v0&255)];               \
                S[nf][1] += sm[AQR + (w*16+tq)*68 + (v0>>8)];                \
                S[nf][2] += sm[AQR + (w*16+tq+8)*68 + (v1&255)];             \
                S[nf][3] += sm[AQR + (w*16+tq+8)*68 + (v1>>8)];              \
            }                                                                \
        }                                                                    \
        float tm0 = -1e30f, tm1 = -1e30f;                                    \
        _Pragma("unroll")                                                    \
        for (int nf=0; nf<8; nf++){                                          \
            tm0 = fmaxf(tm0, fmaxf(S[nf][0], S[nf][1]));                     \
            tm1 = fmaxf(tm1, fmaxf(S[nf][2], S[nf][3]));                     \
        }                                                                    \
        tm0 = fmaxf(tm0, __shfl_xor_sync(0xffffffffu, tm0, 1));              \
        tm0 = fmaxf(tm0, __shfl_xor_sync(0xffffffffu, tm0, 2));              \
        tm1 = fmaxf(tm1, __shfl_xor_sync(0xffffffffu, tm1, 1));              \
        tm1 = fmaxf(tm1, __shfl_xor_sync(0xffffffffu, tm1, 2));              \
        float mn0 = fmaxf(mr0, tm0), mn1 = fmaxf(mr1, tm1);                  \
        float f0 = __expf(mr0 - mn0), f1 = __expf(mr1 - mn1);                \
        mr0 = mn0; mr1 = mn1;                                                \
        float rs0 = 0.f, rs1 = 0.f;                                          \
        _Pragma("unroll")                                                    \
        for (int nf=0; nf<8; nf++){                                          \
            S[nf][0] = __expf(S[nf][0]-mn0); rs0 += S[nf][0];                \
            S[nf][1] = __expf(S[nf][1]-mn0); rs0 += S[nf][1];                \
            S[nf][2] = __expf(S[nf][2]-mn1); rs1 += S[nf][2];                \
            S[nf][3] = __expf(S[nf][3]-mn1); rs1 += S[nf][3];                \
        }                                                                    \
        rs0 += __shfl_xor_sync(0xffffffffu, rs0, 1);                         \
        rs0 += __shfl_xor_sync(0xffffffffu, rs0, 2);                         \
        rs1 += __shfl_xor_sync(0xffffffffu, rs1, 1);                         \
        rs1 += __shfl_xor_sync(0xffffffffu, rs1, 2);                         \
        lr0 = lr0*f0 + rs0; lr1 = lr1*f1 + rs1;                              \
        _Pragma("unroll")                                                    \
        for (int nf=0; nf<8; nf++){                                          \
            O[nf][0]*=f0; O[nf][1]*=f0; O[nf][2]*=f1; O[nf][3]*=f1;          \
        }                                                                    \
        _Pragma("unroll")                                                    \
        for (int nf=0; nf<8; nf++){                                          \
            int c0 = nf*8 + 2*te, c1 = c0+1;                                 \
            int p0 = PERM8(c0), p1 = PERM8(c1);                              \
            smu[APS + (w*16+tq)*68 + p0]   = cvt_tf32(S[nf][0]);             \
            smu[APS + (w*16+tq)*68 + p1]   = cvt_tf32(S[nf][1]);             \
            smu[APS + (w*16+tq+8)*68 + p0] = cvt_tf32(S[nf][2]);             \
            smu[APS + (w*16+tq+8)*68 + p1] = cvt_tf32(S[nf][3]);             \
        }                                                                    \
        __syncwarp();                                                        \
        _Pragma("unroll")                                                    \
        for (int ks=0; ks<8; ks++){                                          \
            uint2 x = *(uint2*)&smu[APS + (w*16+tq)*68 + ks*8 + 2*te];       \
            uint2 y = *(uint2*)&smu[APS + (w*16+tq+8)*68 + ks*8 + 2*te];     \
            _Pragma("unroll")                                                \
            for (int nf=0; nf<8; nf++){                                      \
                uint2 bb = *(uint2*)&smu[(VOFF) + (nf*8+tq)*68 + ks*8 + 2*te];\
                mma_tf32(O[nf], x.x, y.x, x.y, y.y, bb.x, bb.y);             \
            }                                                                \
        }                                                                    \
    }

#define HOIST_Q(KOFF)                                                        \
    {                                                                        \
        _Pragma("unroll")                                                    \
        for (int ks=0; ks<8; ks++){                                          \
            uint2 x = *(uint2*)&smu[(KOFF) + (w*16+tq)*68 + ks*8 + 2*te];    \
            uint2 y = *(uint2*)&smu[(KOFF) + (w*16+tq+8)*68 + ks*8 + 2*te];  \
            qa[ks][0]=x.x; qa[ks][1]=y.x; qa[ks][2]=x.y; qa[ks][3]=y.y;      \
        }                                                                    \
    }
#define WRITE_QR()                                                           \
    {                                                                        \
        _Pragma("unroll")                                                    \
        for (int nf=0; nf<8; nf++){                                          \
            *(float2*)&sm[AQR + (w*16+tq)*68 + nf*8 + 2*te] =                \
                make_float2(S[nf][0], S[nf][1]);                             \
            *(float2*)&sm[AQR + (w*16+tq+8)*68 + nf*8 + 2*te] =              \
                make_float2(S[nf][2], S[nf][3]);                             \
        }                                                                    \
    }
#define ZERO_S()                                                             \
    { _Pragma("unroll")                                                      \
      for (int nf=0;nf<8;nf++){ S[nf][0]=S[nf][1]=S[nf][2]=S[nf][3]=0.f; } }

// -------------------- fused main attention ---------------------------------
// grid (R/64, H, B), 128 threads (4 warps), double-buffered cp.async pipeline
__global__ __launch_bounds__(128,2) void attn_main_kernel(){
    extern __shared__ float sm[];
    unsigned* smu = (unsigned*)sm;
    char* smc = (char*)sm;
    int t = threadIdx.x, lane = t & 31, w = t >> 5;
    int tq = lane >> 2, te = lane & 3;
    int b = blockIdx.z, h = blockIdx.y, bh = b*H_ + h;
    int q0 = blockIdx.x * 64;

    // startup: Q -> KB0, r0 -> VB0
    {
        const unsigned* qg = g_qp + ((size_t)bh*R_ + q0)*64;
        const unsigned* rg = g_r0p + (size_t)h*Z_*64;
        #pragma unroll
        for (int j=0;j<8;j++){
            int c = t + 128*j;
            cp16(&sm[KB(0) + (c>>4)*68 + (c&15)*4], qg + c*4);
            cp16(&sm[VB(0) + (c>>4)*68 + (c&15)*4], rg + c*4);
        }
    }
    CP_COMMIT(); CP_WAIT0(); __syncthreads();

    unsigned qa[8][4];
    HOIST_Q(KB(0));
    float S[8][4];
    ZERO_S();
    SCORE_MMA(S, VB(0));
    WRITE_QR();
    __syncthreads();   // QR visible, KB0/VB0 free

    // prefetch tile 0 (sum keys k2/v2)
    stage_kv(sm, KB(0), VB(0),
             g_k2p + (size_t)bh*S_*64, g_v2t + (size_t)bh*64*S_, S_, t);
    CP_COMMIT();

    float O[8][4];
    #pragma unroll
    for (int nf=0;nf<8;nf++){ O[nf][0]=O[nf][1]=O[nf][2]=O[nf][3]=0.f; }
    float mr0 = -1e30f, mr1 = -1e30f, lr0 = 0.f, lr1 = 0.f;

    const unsigned char* igbase = g_idx8 + ((size_t)b*TOTLEN + S_ + q0)*R_;

    for (int kt = 0; kt < 33; kt++){
        if (kt < 32){
            int k0n = kt*64;
            int nb = (kt+1)&1;
            stage_kv(sm, KB(nb), VB(nb),
                     g_kp + ((size_t)bh*R_ + k0n)*64,
                     g_vt + (size_t)bh*64*R_ + k0n, R_, t);
            stage_ix(smc, IXF(nb)*4, igbase + k0n, t);
            CP_COMMIT(); CP_WAIT1();
        } else {
            CP_WAIT0();
        }
        __syncthreads();
        int bu = kt&1;
        ZERO_S();
        SCORE_MMA(S, KB(bu));
        if (kt == 0){ SOFTMAX_PV(0, 0, VB(bu)); }
        else        { SOFTMAX_PV(1, IXF(bu)*4, VB(bu)); }
        __syncthreads();
    }

    float inv0 = 1.f/lr0, inv1 = 1.f/lr1;
    int qaR = q0 + w*16 + tq;
    #pragma unroll
    for (int nf=0; nf<8; nf++){
        int c = nf*8 + 2*te;
        *(float2*)&g_attn[((size_t)qaR*B_ + b)*E_ + h*64 + c] =
            make_float2(O[nf][0]*inv0, O[nf][1]*inv0);
        *(float2*)&g_attn[((size_t)(qaR+8)*B_ + b)*E_ + h*64 + c] =
            make_float2(O[nf][2]*inv1, O[nf][3]*inv1);
    }
}

// -------------------- fused sum attention (split-K) -------------------------
// grid (B*H, SPLITS), 128 threads; each split covers 256 keys (4 tiles).
__global__ __launch_bounds__(128,2) void attn_sum_kernel(const int* __restrict__ tok,
        const float* __restrict__ emb_sum){
    extern __shared__ float sm[];
    unsigned* smu = (unsigned*)sm;
    char* smc = (char*)sm;
    int t = threadIdx.x, lane = t & 31, w = t >> 5;
    int tq = lane >> 2, te = lane & 3;
    int bh = blockIdx.x, split = blockIdx.y;
    int b = bh >> 4, h = bh & 15;

    {   // gather + scale + cvt + perm sum_q into KB0; r0 -> VB0
        int row = t>>1, halfc = (t&1)*32;
        int token = tok[b*S_ + row];
        const float4* p = (const float4*)(emb_sum + (size_t)token*E_ + h*64 + halfc);
        unsigned* d = smu + KB(0) + row*68;
        #pragma unroll
        for (int j=0;j<8;j++){
            float4 v = p[j];
            int c = halfc + j*4;
            int base = (c & ~7) + ((c>>2)&1);
            d[base+0]=cvt_tf32(v.x*SCALE_); d[base+2]=cvt_tf32(v.y*SCALE_);
            d[base+4]=cvt_tf32(v.z*SCALE_); d[base+6]=cvt_tf32(v.w*SCALE_);
        }
        const unsigned* rg = g_r0p + (size_t)h*Z_*64;
        #pragma unroll
        for (int j=0;j<8;j++){
            int c = t + 128*j;
            cp16(&sm[VB(0) + (c>>4)*68 + (c&15)*4], rg + c*4);
        }
    }
    CP_COMMIT(); CP_WAIT0(); __syncthreads();

    unsigned qa[8][4];
    HOIST_Q(KB(0));
    float S[8][4];
    ZERO_S();
    SCORE_MMA(S, VB(0));
    WRITE_QR();
    __syncthreads();

    const unsigned char* igbase = g_idx8 + (size_t)b*TOTLEN*R_;
    int kbase = split*256;

    stage_kv(sm, KB(0), VB(0),
             g_kp + ((size_t)bh*R_ + kbase)*64,
             g_vt + (size_t)bh*64*R_ + kbase, R_, t);
    stage_ix(smc, IXF(0)*4, igbase + kbase, t);
    CP_COMMIT();

    float O[8][4];
    #pragma unroll
    for (int nf=0;nf<8;nf++){ O[nf][0]=O[nf][1]=O[nf][2]=O[nf][3]=0.f; }
    float mr0 = -1e30f, mr1 = -1e30f, lr0 = 0.f, lr1 = 0.f;

    for (int kt = 0; kt < 4; kt++){
        if (kt < 3){
            int k0n = kbase + (kt+1)*64;
            int nb = (kt+1)&1;
            stage_kv(sm, KB(nb), VB(nb),
                     g_kp + ((size_t)bh*R_ + k0n)*64,
                     g_vt + (size_t)bh*64*R_ + k0n, R_, t);
            stage_ix(smc, IXF(nb)*4, igbase + k0n, t);
            CP_COMMIT(); CP_WAIT1();
        } else {
            CP_WAIT0();
        }
        __syncthreads();
        int bu = kt&1;
        ZERO_S();
        SCORE_MMA(S, KB(bu));
        SOFTMAX_PV(1, IXF(bu)*4, VB(bu));
        __syncthreads();
    }

    int pb = bh*SPLITS + split;
    int s0 = w*16 + tq;
    #pragma unroll
    for (int nf=0; nf<8; nf++){
        int c = nf*8 + 2*te;
        *(float2*)&g_pacc[((size_t)pb*S_ + s0)*64 + c] =
            make_float2(O[nf][0], O[nf][1]);
        *(float2*)&g_pacc[((size_t)pb*S_ + s0 + 8)*64 + c] =
            make_float2(O[nf][2], O[nf][3]);
    }
    if (te == 0){
        g_pm[pb*S_ + s0] = mr0;    g_pm[pb*S_ + s0 + 8] = mr1;
        g_pl[pb*S_ + s0] = lr0;    g_pl[pb*S_ + s0 + 8] = lr1;
    }
}

// -------- combine split-K partials -> g_sumx2 -------------------------------
__global__ __launch_bounds__(64) void combine_kernel(){
    int rowq = blockIdx.x;            // bh*64 + s
    int bh = rowq >> 6, s = rowq & 63;
    int d = threadIdx.x;
    float mv[SPLITS];
    float M = -1e30f;
    #pragma unroll
    for (int i=0;i<SPLITS;i++){
        mv[i] = g_pm[(bh*SPLITS + i)*S_ + s];
        M = fmaxf(M, mv[i]);
    }
    float L = 0.f, acc = 0.f;
    #pragma unroll
    for (int i=0;i<SPLITS;i++){
        float w = __expf(mv[i] - M);
        acc += w * g_pacc[((size_t)(bh*SPLITS + i)*S_ + s)*64 + d];
        L   += w * g_pl[(bh*SPLITS + i)*S_ + s];
    }
    g_sumx2[(bh*S_ + s)*64 + d] = acc / L;
}

// -------- per-row (b,h,s) projections sum_k2/sum_v2 with LN -> tf32 layouts -
__global__ __launch_bounds__(64) void k2v2_kernel(const float* __restrict__ Wk2,
        const float* __restrict__ bk2, const float* __restrict__ Wv2,
        const float* __restrict__ bv2, const float* __restrict__ g1,
        const float* __restrict__ b1, const float* __restrict__ g2,
        const float* __restrict__ b2){
    __shared__ float xr[64];
    __shared__ float red[2];
    int row = blockIdx.x, t = threadIdx.x;
    int bh = row >> 6, s = row & 63;
    xr[t] = g_sumx2[row*64 + t];
    __syncthreads();
    #pragma unroll
    for (int pass=0; pass<2; pass++){
        const float* W  = pass ? Wv2 : Wk2;
        const float* bb = pass ? bv2 : bk2;
        const float* gg = pass ? g2  : g1;
        const float* bt = pass ? b2  : b1;
        float a = bb[t];
        #pragma unroll 8
        for (int j=0;j<64;j++) a += xr[j]*W[j*64+t];
        float sred = a;
        #pragma unroll
        for (int o=16;o;o>>=1) sred += __shfl_xor_sync(0xffffffffu, sred, o);
        if ((t&31)==0) red[t>>5] = sred;
        __syncthreads();
        float mean = (red[0]+red[1]) * (1.f/64.f);
        __syncthreads();
        float dv = a - mean;
        float v2 = dv*dv;
        #pragma unroll
        for (int o=16;o;o>>=1) v2 += __shfl_xor_sync(0xffffffffu, v2, o);
        if ((t&31)==0) red[t>>5] = v2;
        __syncthreads();
        float var = (red[0]+red[1]) * (1.f/64.f);
        __syncthreads();
        float outv = dv*rsqrtf(var+1e-5f)*gg[t] + bt[t];
        if (pass == 0)
            g_k2p[(size_t)row*64 + PERM8(t)] = cvt_tf32(outv);
        else
            g_v2t[((size_t)bh*64 + t)*64 + PERM8(s)] = cvt_tf32(outv);
    }
}

// ---------------------------------------------------------------------------
extern "C" void kernel_launch(void* const* d_in, const int* in_sizes, int n_in,
                              void* d_out, int out_size){
    const float* reg_x   = (const float*)d_in[0];
    const int*   tok     = (const int*)d_in[1];
    const int*   rel_idx = (const int*)d_in[2];
    const float* emb_sum  = (const float*)d_in[5];
    const float* rel_emb0 = (const float*)d_in[6];
    const float* Wq  = (const float*)d_in[7];  const float* bq  = (const float*)d_in[8];
    const float* Wk  = (const float*)d_in[9];  const float* bk  = (const float*)d_in[10];
    const float* Wv  = (const float*)d_in[11]; const float* bv  = (const float*)d_in[12];
    const float* Wr0 = (const float*)d_in[13]; const float* br0 = (const float*)d_in[14];
    const float* Wk2 = (const float*)d_in[15]; const float* bk2 = (const float*)d_in[16];
    const float* Wv2 = (const float*)d_in[17]; const float* bv2 = (const float*)d_in[18];
    const float* Wo  = (const float*)d_in[19]; const float* bo  = (const float*)d_in[20];
    const float* lnkg  = (const float*)d_in[21]; const float* lnkb  = (const float*)d_in[22];
    const float* lnvg  = (const float*)d_in[23]; const float* lnvb  = (const float*)d_in[24];
    const float* lnk2g = (const float*)d_in[25]; const float* lnk2b = (const float*)d_in[26];
    const float* lnv2g = (const float*)d_in[27]; const float* lnv2b = (const float*)d_in[28];
    float* out = (float*)d_out;

    cudaFuncSetAttribute(attn_sum_kernel,  cudaFuncAttributeMaxDynamicSharedMemorySize, ATTN_SMEM_BYTES);
    cudaFuncSetAttribute(attn_main_kernel, cudaFuncAttributeMaxDynamicSharedMemorySize, ATTN_SMEM_BYTES);

    float *tq_, *tk_, *tv_, *gattn;
    cudaGetSymbolAddress((void**)&tq_, g_tmp_q);
    cudaGetSymbolAddress((void**)&tk_, g_tmp_k);
    cudaGetSymbolAddress((void**)&tv_, g_tmp_v);
    cudaGetSymbolAddress((void**)&gattn, g_attn);

    dim3 ggrid(E_/128, MROWS/128);   // (8, 32)
    gemm_bias<<<ggrid, 256>>>(reg_x, Wq, bq, tq_);
    gemm_bias<<<ggrid, 256>>>(reg_x, Wk, bk, tk_);
    gemm_bias<<<ggrid, 256>>>(reg_x, Wv, bv, tv_);

    reorg_kernel<<<MROWS*H_/8, 256>>>(tq_, (const float*)0, (const float*)0, 0);
    reorg_kernel<<<MROWS*H_/8, 256>>>(tk_, lnkg, lnkb, 1);
    reorg_kernel<<<MROWS*H_/8, 256>>>(tv_, lnvg, lnvb, 2);

    r0_kernel<<<Z_*H_, 64>>>(rel_emb0, Wr0, br0);
    idx8_kernel<<<(B_*TOTLEN*R_/4 + 255)/256, 256>>>(rel_idx);

    attn_sum_kernel<<<dim3(B_*H_, SPLITS), 128, ATTN_SMEM_BYTES>>>(tok, emb_sum);
    combine_kernel<<<B_*H_*S_, 64>>>();
    k2v2_kernel<<<B_*H_*S_, 64>>>(Wk2, bk2, Wv2, bv2, lnk2g, lnk2b, lnv2g, lnv2b);

    attn_main_kernel<<<dim3(R_/64, H_, B_), 128, ATTN_SMEM_BYTES>>>();

    gemm_bias<<<ggrid, 256>>>(gattn, Wo, bo, out);
}

// round 5
// speedup vs baseline: 7.3675x; 1.2098x over previous
#include <cuda_runtime.h>
#include <math.h>

#define H_ 16
#define D_ 64
#define R_ 2048
#define S_ 64
#define B_ 2
#define E_ 1024
#define Z_ 64
#define SCALE_ 0.125f
#define MROWS (R_*B_)   /* 4096 */
#define SPLITS 8
#define TOTLEN (S_+R_)  /* 2112 */

// ---------------- scratch (device globals: allocation-free) ----------------
__device__ unsigned g_xp[MROWS*E_];       // reg_x tf32 [m][k-perm]
__device__ unsigned g_attnp[MROWS*E_];    // attn out tf32 [m][k-perm]
__device__ unsigned g_Wqp[E_*E_];         // W tf32 [n][k-perm]
__device__ unsigned g_Wkp[E_*E_];
__device__ unsigned g_Wvp[E_*E_];
__device__ unsigned g_Wop[E_*E_];
__device__ unsigned g_qp[B_*H_*R_*D_];    // Q tf32, [bh][r][d-perm], scaled
__device__ unsigned g_kp[B_*H_*R_*D_];    // K tf32, [bh][r][d-perm]
__device__ unsigned g_vt[B_*H_*D_*R_];    // V tf32, [bh][d][r-perm]
__device__ unsigned g_r0p[H_*Z_*D_];      // r0 tf32, [h][z][d-perm]
__device__ unsigned g_k2p[B_*H_*S_*D_];   // k2 tf32, [bh][s][d-perm]
__device__ unsigned g_v2t[B_*H_*D_*S_];   // v2 tf32, [bh][d][s-perm]
__device__ unsigned char g_idx8[B_*TOTLEN*R_];
__device__ float g_sumx2[B_*H_*S_*D_];
__device__ float g_pacc[B_*H_*SPLITS*S_*D_];
__device__ float g_pm[B_*H_*SPLITS*S_];
__device__ float g_pl[B_*H_*SPLITS*S_];

#define PERM8(c) ((((c)) & ~7) + 2*((c)&3) + (((c)>>2)&1))

// ---------------- tf32 / async helpers -------------------------------------
__device__ __forceinline__ unsigned cvt_tf32(float x){
    unsigned u; asm("cvt.rna.tf32.f32 %0, %1;" : "=r"(u) : "f"(x)); return u;
}
__device__ __forceinline__ void mma_tf32(float* c,
        unsigned a0, unsigned a1, unsigned a2, unsigned a3,
        unsigned b0, unsigned b1){
    asm volatile(
        "mma.sync.aligned.m16n8k8.row.col.f32.tf32.tf32.f32 "
        "{%0,%1,%2,%3},{%4,%5,%6,%7},{%8,%9},{%0,%1,%2,%3};"
        : "+f"(c[0]), "+f"(c[1]), "+f"(c[2]), "+f"(c[3])
        : "r"(a0), "r"(a1), "r"(a2), "r"(a3), "r"(b0), "r"(b1));
}
__device__ __forceinline__ void cp16(void* dst, const void* src){
    unsigned d = (unsigned)__cvta_generic_to_shared(dst);
    asm volatile("cp.async.cg.shared.global [%0],[%1],16;" :: "r"(d), "l"(src));
}
#define CP_COMMIT() asm volatile("cp.async.commit_group;" ::: "memory")
#define CP_WAIT0()  asm volatile("cp.async.wait_group 0;" ::: "memory")
#define CP_WAIT1()  asm volatile("cp.async.wait_group 1;" ::: "memory")

// -------- pre-conversion kernels -------------------------------------------
// A[m][k] f32 -> [m][k-perm] tf32
__global__ __launch_bounds__(256) void cvtA_kernel(const float* __restrict__ src,
        unsigned* __restrict__ dst){
    size_t i = (size_t)blockIdx.x*256 + threadIdx.x;
    size_t m = i >> 8; int kq = (int)(i & 255) * 4;
    float4 v = *(const float4*)(src + m*E_ + kq);
    unsigned* d = dst + m*E_ + (kq & ~7) + ((kq>>2)&1);
    d[0]=cvt_tf32(v.x); d[2]=cvt_tf32(v.y); d[4]=cvt_tf32(v.z); d[6]=cvt_tf32(v.w);
}
// W[k][n] f32 -> [n][k-perm] tf32 (transpose)
__global__ void cvtW_kernel(const float* __restrict__ W, unsigned* __restrict__ out){
    __shared__ float tile[32][33];
    int k0 = blockIdx.y*32, n0 = blockIdx.x*32;
    int tx = threadIdx.x, ty = threadIdx.y;  // 32 x 8
    #pragma unroll
    for (int j=0;j<4;j++)
        tile[ty+8*j][tx] = W[(size_t)(k0+ty+8*j)*E_ + n0 + tx];
    __syncthreads();
    #pragma unroll
    for (int j=0;j<4;j++){
        int n = n0 + ty + 8*j;
        int k = k0 + tx;
        out[(size_t)n*E_ + (k & ~7) + 2*(k&3) + ((k>>2)&1)] = cvt_tf32(tile[tx][ty+8*j]);
    }
}

// ---------------- fused GEMM + epilogue ------------------------------------
// C[4096,1024] = A[4096,1024] @ W^T(n-major) + bias, tile 128x128, BK=32,
// 256 thr / 8 warps, warp tile 32m x 64n, double-buffered cp.async.
// mode 0: Q (scale, perm store)  1: K (LN, perm)  2: V (LN, transposed perm)
// mode 3: plain f32 out + bias
#define GA(b) ((b)*9216)
#define GB(b) (4608 + (b)*9216)
#define GEMM_SMEM_BYTES (18432*4)

__device__ __forceinline__ void g_stage(unsigned* smg, int ab, int bb_,
        const unsigned* Ag, const unsigned* Wg, int t){
    #pragma unroll
    for (int j=0;j<4;j++){
        int c = t + 256*j; int row = c>>3, col = (c&7)*4;
        cp16(&smg[ab + row*36 + col], Ag + (size_t)row*E_ + col);
        cp16(&smg[bb_ + row*36 + col], Wg + (size_t)row*E_ + col);
    }
}

__global__ __launch_bounds__(256) void gemm_fused(const unsigned* __restrict__ A,
        const unsigned* __restrict__ W, const float* __restrict__ bias,
        float* __restrict__ outF, int mode,
        const float* __restrict__ gg, const float* __restrict__ bb){
    extern __shared__ unsigned smg[];
    int t = threadIdx.x, lane = t & 31, w = t >> 5;
    int wm = w >> 1, wn = w & 1;
    int tq = lane >> 2, te = lane & 3;
    int row0 = blockIdx.y * 128, n0 = blockIdx.x * 128;
    const unsigned* Abase = A + (size_t)row0*E_;
    const unsigned* Wbase = W + (size_t)n0*E_;

    float acc[2][8][4];
    #pragma unroll
    for (int m=0;m<2;m++)
        #pragma unroll
        for (int n=0;n<8;n++)
            #pragma unroll
            for (int j=0;j<4;j++) acc[m][n][j]=0.f;

    g_stage(smg, GA(0), GB(0), Abase, Wbase, t);
    CP_COMMIT();

    for (int it=0; it<32; it++){
        if (it < 31){
            g_stage(smg, GA((it+1)&1), GB((it+1)&1),
                    Abase + (it+1)*32, Wbase + (it+1)*32, t);
            CP_COMMIT(); CP_WAIT1();
        } else {
            CP_WAIT0();
        }
        __syncthreads();
        int abo = GA(it&1), bbo = GB(it&1);
        #pragma unroll
        for (int ks=0; ks<4; ks++){
            unsigned a[2][4];
            #pragma unroll
            for (int mf=0; mf<2; mf++){
                int row = wm*32 + mf*16 + tq;
                uint2 x = *(uint2*)&smg[abo + row*36 + ks*8 + 2*te];
                uint2 y = *(uint2*)&smg[abo + (row+8)*36 + ks*8 + 2*te];
                a[mf][0]=x.x; a[mf][1]=y.x; a[mf][2]=x.y; a[mf][3]=y.y;
            }
            #pragma unroll
            for (int nf=0; nf<8; nf++){
                uint2 bv = *(uint2*)&smg[bbo + (wn*64+nf*8+tq)*36 + ks*8 + 2*te];
                mma_tf32(acc[0][nf], a[0][0],a[0][1],a[0][2],a[0][3], bv.x,bv.y);
                mma_tf32(acc[1][nf], a[1][0],a[1][1],a[1][2],a[1][3], bv.x,bv.y);
            }
        }
        __syncthreads();
    }

    int h = blockIdx.x*2 + wn;
    #pragma unroll
    for (int mf=0; mf<2; mf++){
        #pragma unroll
        for (int rsel=0; rsel<2; rsel++){
            int m = row0 + wm*32 + mf*16 + tq + rsel*8;
            float v[16];
            #pragma unroll
            for (int nf=0; nf<8; nf++){
                int c = nf*8 + 2*te;
                v[2*nf]   = acc[mf][nf][2*rsel]   + __ldg(&bias[h*64 + c]);
                v[2*nf+1] = acc[mf][nf][2*rsel+1] + __ldg(&bias[h*64 + c + 1]);
            }
            if (mode == 3){
                #pragma unroll
                for (int nf=0; nf<8; nf++)
                    *(float2*)&outF[(size_t)m*E_ + h*64 + nf*8 + 2*te] =
                        make_float2(v[2*nf], v[2*nf+1]);
            } else if (mode == 0){
                int r = m>>1, b = m&1, bh = b*H_ + h;
                unsigned* dst = g_qp + ((size_t)bh*R_ + r)*64;
                #pragma unroll
                for (int nf=0; nf<8; nf++){
                    int c = nf*8 + 2*te;
                    dst[PERM8(c)]   = cvt_tf32(v[2*nf]*SCALE_);
                    dst[PERM8(c+1)] = cvt_tf32(v[2*nf+1]*SCALE_);
                }
            } else {
                int r = m>>1, b = m&1, bh = b*H_ + h;
                float s = 0.f;
                #pragma unroll
                for (int i=0;i<16;i++) s += v[i];
                s += __shfl_xor_sync(0xffffffffu, s, 1);
                s += __shfl_xor_sync(0xffffffffu, s, 2);
                float mean = s*(1.f/64.f);
                float var = 0.f;
                #pragma unroll
                for (int i=0;i<16;i++){ float d = v[i]-mean; var += d*d; }
                var += __shfl_xor_sync(0xffffffffu, var, 1);
                var += __shfl_xor_sync(0xffffffffu, var, 2);
                float scl = rsqrtf(var*(1.f/64.f) + 1e-5f);
                if (mode == 1){
                    unsigned* dst = g_kp + ((size_t)bh*R_ + r)*64;
                    #pragma unroll
                    for (int nf=0; nf<8; nf++){
                        int c = nf*8 + 2*te;
                        dst[PERM8(c)]   = cvt_tf32((v[2*nf]-mean)*scl*__ldg(&gg[c]) + __ldg(&bb[c]));
                        dst[PERM8(c+1)] = cvt_tf32((v[2*nf+1]-mean)*scl*__ldg(&gg[c+1]) + __ldg(&bb[c+1]));
                    }
                } else {
                    int rp = PERM8(r);
                    #pragma unroll
                    for (int nf=0; nf<8; nf++){
                        int c = nf*8 + 2*te;
                        g_vt[((size_t)bh*64 + c)*R_ + rp] =
                            cvt_tf32((v[2*nf]-mean)*scl*__ldg(&gg[c]) + __ldg(&bb[c]));
                        g_vt[((size_t)bh*64 + c+1)*R_ + rp] =
                            cvt_tf32((v[2*nf+1]-mean)*scl*__ldg(&gg[c+1]) + __ldg(&bb[c+1]));
                    }
                }
            }
        }
    }
}

// -------- r0p[h][z][dperm] = tf32( rel_emb0@Wr0 + br0 ) ---------------------
__global__ __launch_bounds__(64) void r0_kernel(const float* __restrict__ rel_emb0,
        const float* __restrict__ Wr0, const float* __restrict__ br0){
    int z = blockIdx.x >> 4, h = blockIdx.x & 15;
    int d = threadIdx.x;
    float a = br0[h*64+d];
    #pragma unroll 8
    for (int c=0;c<64;c++) a += rel_emb0[z*64+c]*Wr0[c*E_ + h*64 + d];
    g_r0p[(h*Z_ + z)*64 + PERM8(d)] = cvt_tf32(a);
}

// -------- compress rel_idx (int32 < 64) to u8 -------------------------------
__global__ __launch_bounds__(256) void idx8_kernel(const int* __restrict__ rel){
    size_t i = (size_t)blockIdx.x*256 + threadIdx.x;
    int4 v = ((const int4*)rel)[i];
    uchar4 u; u.x=(unsigned char)v.x; u.y=(unsigned char)v.y;
    u.z=(unsigned char)v.z; u.w=(unsigned char)v.w;
    ((uchar4*)g_idx8)[i] = u;
}

// ---------------- attention smem layout (floats) ---------------------------
#define KB(b)  ((b)*4352)            /* K tile [64 keys][68], tf32 perm */
#define VB(b)  (8704 + (b)*4352)     /* Vt tile [64 d][68], tf32 key-perm */
#define IXF(b) (17408 + (b)*1280)    /* idx u8 [64 q][80 bytes] */
#define AQR    19968                 /* qr fp32 [64 q][68] plain cols */
#define APS    24320                 /* P tf32 [64 q][68] perm cols */
#define ATTN_SMEM_F 28672
#define ATTN_SMEM_BYTES (ATTN_SMEM_F*4)   /* 114688 */

__device__ __forceinline__ void stage_kv(float* sm, int kbo, int vbo,
        const unsigned* kg, const unsigned* vg, long vstride, int t){
    #pragma unroll
    for (int j=0;j<8;j++){
        int c = t + 128*j;
        cp16(&sm[kbo + (c>>4)*68 + (c&15)*4], kg + c*4);
        cp16(&sm[vbo + (c>>4)*68 + (c&15)*4], vg + (long)(c>>4)*vstride + (c&15)*4);
    }
}
__device__ __forceinline__ void stage_ix(char* smc, int ixbyte,
        const unsigned char* ig, int t){
    #pragma unroll
    for (int j=0;j<2;j++){
        int c = t + 128*j;
        cp16(smc + ixbyte + (c>>2)*80 + (c&3)*16, ig + (size_t)(c>>2)*R_ + (c&3)*16);
    }
}

#define SCORE_MMA(SREG, KOFF)                                                \
    {                                                                        \
        _Pragma("unroll")                                                    \
        for (int ks=0; ks<8; ks++){                                          \
            _Pragma("unroll")                                                \
            for (int nf=0; nf<8; nf++){                                      \
                uint2 bb = *(uint2*)&smu[(KOFF) + (nf*8+tq)*68 + ks*8 + 2*te];\
                mma_tf32(SREG[nf], qa[ks][0],qa[ks][1],qa[ks][2],qa[ks][3],  \
                         bb.x, bb.y);                                        \
            }                                                                \
        }                                                                    \
    }

#define SOFTMAX_PV(USE_BIAS, IXBYTE, VOFF)                                   \
    {                                                                        \
        if (USE_BIAS){                                                       \
            const unsigned char* ixb = (const unsigned char*)smc + (IXBYTE); \
            _Pragma("unroll")                                                \
            for (int nf=0; nf<8; nf++){                                      \
                unsigned v0 = *(const unsigned short*)                       \
                    (ixb + (w*16+tq)*80 + nf*8 + 2*te);                      \
                unsigned v1 = *(const unsigned short*)                       \
                    (ixb + (w*16+tq+8)*80 + nf*8 + 2*te);                    \
                S[nf][0] += sm[AQR + (w*16+tq)*68 + (v0&255)];               \
                S[nf][1] += sm[AQR + (w*16+tq)*68 + (v0>>8)];                \
                S[nf][2] += sm[AQR + (w*16+tq+8)*68 + (v1&255)];             \
                S[nf][3] += sm[AQR + (w*16+tq+8)*68 + (v1>>8)];              \
            }                                                                \
        }                                                                    \
        float tm0 = -1e30f, tm1 = -1e30f;                                    \
        _Pragma("unroll")                                                    \
        for (int nf=0; nf<8; nf++){                                          \
            tm0 = fmaxf(tm0, fmaxf(S[nf][0], S[nf][1]));                     \
            tm1 = fmaxf(tm1, fmaxf(S[nf][2], S[nf][3]));                     \
        }                                                                    \
        tm0 = fmaxf(tm0, __shfl_xor_sync(0xffffffffu, tm0, 1));              \
        tm0 = fmaxf(tm0, __shfl_xor_sync(0xffffffffu, tm0, 2));              \
        tm1 = fmaxf(tm1, __shfl_xor_sync(0xffffffffu, tm1, 1));              \
        tm1 = fmaxf(tm1, __shfl_xor_sync(0xffffffffu, tm1, 2));              \
        float mn0 = fmaxf(mr0, tm0), mn1 = fmaxf(mr1, tm1);                  \
        float f0 = __expf(mr0 - mn0), f1 = __expf(mr1 - mn1);                \
        mr0 = mn0; mr1 = mn1;                                                \
        float rs0 = 0.f, rs1 = 0.f;                                          \
        _Pragma("unroll")                                                    \
        for (int nf=0; nf<8; nf++){                                          \
            S[nf][0] = __expf(S[nf][0]-mn0); rs0 += S[nf][0];                \
            S[nf][1] = __expf(S[nf][1]-mn0); rs0 += S[nf][1];                \
            S[nf][2] = __expf(S[nf][2]-mn1); rs1 += S[nf][2];                \
            S[nf][3] = __expf(S[nf][3]-mn1); rs1 += S[nf][3];                \
        }                                                                    \
        rs0 += __shfl_xor_sync(0xffffffffu, rs0, 1);                         \
        rs0 += __shfl_xor_sync(0xffffffffu, rs0, 2);                         \
        rs1 += __shfl_xor_sync(0xffffffffu, rs1, 1);                         \
        rs1 += __shfl_xor_sync(0xffffffffu, rs1, 2);                         \
        lr0 = lr0*f0 + rs0; lr1 = lr1*f1 + rs1;                              \
        _Pragma("unroll")                                                    \
        for (int nf=0; nf<8; nf++){                                          \
            O[nf][0]*=f0; O[nf][1]*=f0; O[nf][2]*=f1; O[nf][3]*=f1;          \
        }                                                                    \
        _Pragma("unroll")                                                    \
        for (int nf=0; nf<8; nf++){                                          \
            int c0 = nf*8 + 2*te, c1 = c0+1;                                 \
            int p0 = PERM8(c0), p1 = PERM8(c1);                              \
            smu[APS + (w*16+tq)*68 + p0]   = cvt_tf32(S[nf][0]);             \
            smu[APS + (w*16+tq)*68 + p1]   = cvt_tf32(S[nf][1]);             \
            smu[APS + (w*16+tq+8)*68 + p0] = cvt_tf32(S[nf][2]);             \
            smu[APS + (w*16+tq+8)*68 + p1] = cvt_tf32(S[nf][3]);             \
        }                                                                    \
        __syncwarp();                                                        \
        _Pragma("unroll")                                                    \
        for (int ks=0; ks<8; ks++){                                          \
            uint2 x = *(uint2*)&smu[APS + (w*16+tq)*68 + ks*8 + 2*te];       \
            uint2 y = *(uint2*)&smu[APS + (w*16+tq+8)*68 + ks*8 + 2*te];     \
            _Pragma("unroll")                                                \
            for (int nf=0; nf<8; nf++){                                      \
                uint2 bb = *(uint2*)&smu[(VOFF) + (nf*8+tq)*68 + ks*8 + 2*te];\
                mma_tf32(O[nf], x.x, y.x, x.y, y.y, bb.x, bb.y);             \
            }                                                                \
        }                                                                    \
    }

#define HOIST_Q(KOFF)                                                        \
    {                                                                        \
        _Pragma("unroll")                                                    \
        for (int ks=0; ks<8; ks++){                                          \
            uint2 x = *(uint2*)&smu[(KOFF) + (w*16+tq)*68 + ks*8 + 2*te];    \
            uint2 y = *(uint2*)&smu[(KOFF) + (w*16+tq+8)*68 + ks*8 + 2*te];  \
            qa[ks][0]=x.x; qa[ks][1]=y.x; qa[ks][2]=x.y; qa[ks][3]=y.y;      \
        }                                                                    \
    }
#define WRITE_QR()                                                           \
    {                                                                        \
        _Pragma("unroll")                                                    \
        for (int nf=0; nf<8; nf++){                                          \
            *(float2*)&sm[AQR + (w*16+tq)*68 + nf*8 + 2*te] =                \
                make_float2(S[nf][0], S[nf][1]);                             \
            *(float2*)&sm[AQR + (w*16+tq+8)*68 + nf*8 + 2*te] =              \
                make_float2(S[nf][2], S[nf][3]);                             \
        }                                                                    \
    }
#define ZERO_S()                                                             \
    { _Pragma("unroll")                                                      \
      for (int nf=0;nf<8;nf++){ S[nf][0]=S[nf][1]=S[nf][2]=S[nf][3]=0.f; } }

// -------------------- fused main attention ---------------------------------
__global__ __launch_bounds__(128,2) void attn_main_kernel(){
    extern __shared__ float sm[];
    unsigned* smu = (unsigned*)sm;
    char* smc = (char*)sm;
    int t = threadIdx.x, lane = t & 31, w = t >> 5;
    int tq = lane >> 2, te = lane & 3;
    int b = blockIdx.z, h = blockIdx.y, bh = b*H_ + h;
    int q0 = blockIdx.x * 64;

    {
        const unsigned* qg = g_qp + ((size_t)bh*R_ + q0)*64;
        const unsigned* rg = g_r0p + (size_t)h*Z_*64;
        #pragma unroll
        for (int j=0;j<8;j++){
            int c = t + 128*j;
            cp16(&sm[KB(0) + (c>>4)*68 + (c&15)*4], qg + c*4);
            cp16(&sm[VB(0) + (c>>4)*68 + (c&15)*4], rg + c*4);
        }
    }
    CP_COMMIT(); CP_WAIT0(); __syncthreads();

    unsigned qa[8][4];
    HOIST_Q(KB(0));
    float S[8][4];
    ZERO_S();
    SCORE_MMA(S, VB(0));
    WRITE_QR();
    __syncthreads();

    stage_kv(sm, KB(0), VB(0),
             g_k2p + (size_t)bh*S_*64, g_v2t + (size_t)bh*64*S_, S_, t);
    CP_COMMIT();

    float O[8][4];
    #pragma unroll
    for (int nf=0;nf<8;nf++){ O[nf][0]=O[nf][1]=O[nf][2]=O[nf][3]=0.f; }
    float mr0 = -1e30f, mr1 = -1e30f, lr0 = 0.f, lr1 = 0.f;

    const unsigned char* igbase = g_idx8 + ((size_t)b*TOTLEN + S_ + q0)*R_;

    for (int kt = 0; kt < 33; kt++){
        if (kt < 32){
            int k0n = kt*64;
            int nb = (kt+1)&1;
            stage_kv(sm, KB(nb), VB(nb),
                     g_kp + ((size_t)bh*R_ + k0n)*64,
                     g_vt + (size_t)bh*64*R_ + k0n, R_, t);
            stage_ix(smc, IXF(nb)*4, igbase + k0n, t);
            CP_COMMIT(); CP_WAIT1();
        } else {
            CP_WAIT0();
        }
        __syncthreads();
        int bu = kt&1;
        ZERO_S();
        SCORE_MMA(S, KB(bu));
        if (kt == 0){ SOFTMAX_PV(0, 0, VB(bu)); }
        else        { SOFTMAX_PV(1, IXF(bu)*4, VB(bu)); }
        __syncthreads();
    }

    float inv0 = 1.f/lr0, inv1 = 1.f/lr1;
    int qaR = q0 + w*16 + tq;
    unsigned* dst0 = g_attnp + ((size_t)(qaR*B_ + b))*E_ + h*64;
    unsigned* dst1 = g_attnp + ((size_t)((qaR+8)*B_ + b))*E_ + h*64;
    #pragma unroll
    for (int nf=0; nf<8; nf++){
        int c = nf*8 + 2*te;
        dst0[PERM8(c)]   = cvt_tf32(O[nf][0]*inv0);
        dst0[PERM8(c+1)] = cvt_tf32(O[nf][1]*inv0);
        dst1[PERM8(c)]   = cvt_tf32(O[nf][2]*inv1);
        dst1[PERM8(c+1)] = cvt_tf32(O[nf][3]*inv1);
    }
}

// -------------------- fused sum attention (split-K) -------------------------
__global__ __launch_bounds__(128,2) void attn_sum_kernel(const int* __restrict__ tok,
        const float* __restrict__ emb_sum){
    extern __shared__ float sm[];
    unsigned* smu = (unsigned*)sm;
    char* smc = (char*)sm;
    int t = threadIdx.x, lane = t & 31, w = t >> 5;
    int tq = lane >> 2, te = lane & 3;
    int bh = blockIdx.x, split = blockIdx.y;
    int b = bh >> 4, h = bh & 15;

    {
        int row = t>>1, halfc = (t&1)*32;
        int token = tok[b*S_ + row];
        const float4* p = (const float4*)(emb_sum + (size_t)token*E_ + h*64 + halfc);
        unsigned* d = smu + KB(0) + row*68;
        #pragma unroll
        for (int j=0;j<8;j++){
            float4 v = p[j];
            int c = halfc + j*4;
            int base = (c & ~7) + ((c>>2)&1);
            d[base+0]=cvt_tf32(v.x*SCALE_); d[base+2]=cvt_tf32(v.y*SCALE_);
            d[base+4]=cvt_tf32(v.z*SCALE_); d[base+6]=cvt_tf32(v.w*SCALE_);
        }
        const unsigned* rg = g_r0p + (size_t)h*Z_*64;
        #pragma unroll
        for (int j=0;j<8;j++){
            int c = t + 128*j;
            cp16(&sm[VB(0) + (c>>4)*68 + (c&15)*4], rg + c*4);
        }
    }
    CP_COMMIT(); CP_WAIT0(); __syncthreads();

    unsigned qa[8][4];
    HOIST_Q(KB(0));
    float S[8][4];
    ZERO_S();
    SCORE_MMA(S, VB(0));
    WRITE_QR();
    __syncthreads();

    const unsigned char* igbase = g_idx8 + (size_t)b*TOTLEN*R_;
    int kbase = split*256;

    stage_kv(sm, KB(0), VB(0),
             g_kp + ((size_t)bh*R_ + kbase)*64,
             g_vt + (size_t)bh*64*R_ + kbase, R_, t);
    stage_ix(smc, IXF(0)*4, igbase + kbase, t);
    CP_COMMIT();

    float O[8][4];
    #pragma unroll
    for (int nf=0;nf<8;nf++){ O[nf][0]=O[nf][1]=O[nf][2]=O[nf][3]=0.f; }
    float mr0 = -1e30f, mr1 = -1e30f, lr0 = 0.f, lr1 = 0.f;

    for (int kt = 0; kt < 4; kt++){
        if (kt < 3){
            int k0n = kbase + (kt+1)*64;
            int nb = (kt+1)&1;
            stage_kv(sm, KB(nb), VB(nb),
                     g_kp + ((size_t)bh*R_ + k0n)*64,
                     g_vt + (size_t)bh*64*R_ + k0n, R_, t);
            stage_ix(smc, IXF(nb)*4, igbase + k0n, t);
            CP_COMMIT(); CP_WAIT1();
        } else {
            CP_WAIT0();
        }
        __syncthreads();
        int bu = kt&1;
        ZERO_S();
        SCORE_MMA(S, KB(bu));
        SOFTMAX_PV(1, IXF(bu)*4, VB(bu));
        __syncthreads();
    }

    int pb = bh*SPLITS + split;
    int s0 = w*16 + tq;
    #pragma unroll
    for (int nf=0; nf<8; nf++){
        int c = nf*8 + 2*te;
        *(float2*)&g_pacc[((size_t)pb*S_ + s0)*64 + c] =
            make_float2(O[nf][0], O[nf][1]);
        *(float2*)&g_pacc[((size_t)pb*S_ + s0 + 8)*64 + c] =
            make_float2(O[nf][2], O[nf][3]);
    }
    if (te == 0){
        g_pm[pb*S_ + s0] = mr0;    g_pm[pb*S_ + s0 + 8] = mr1;
        g_pl[pb*S_ + s0] = lr0;    g_pl[pb*S_ + s0 + 8] = lr1;
    }
}

// -------- combine split-K partials -> g_sumx2 -------------------------------
__global__ __launch_bounds__(64) void combine_kernel(){
    int rowq = blockIdx.x;
    int bh = rowq >> 6, s = rowq & 63;
    int d = threadIdx.x;
    float mv[SPLITS];
    float M = -1e30f;
    #pragma unroll
    for (int i=0;i<SPLITS;i++){
        mv[i] = g_pm[(bh*SPLITS + i)*S_ + s];
        M = fmaxf(M, mv[i]);
    }
    float L = 0.f, acc = 0.f;
    #pragma unroll
    for (int i=0;i<SPLITS;i++){
        float w = __expf(mv[i] - M);
        acc += w * g_pacc[((size_t)(bh*SPLITS + i)*S_ + s)*64 + d];
        L   += w * g_pl[(bh*SPLITS + i)*S_ + s];
    }
    g_sumx2[(bh*S_ + s)*64 + d] = acc / L;
}

// -------- per-row (b,h,s) projections sum_k2/sum_v2 with LN -> tf32 layouts -
__global__ __launch_bounds__(64) void k2v2_kernel(const float* __restrict__ Wk2,
        const float* __restrict__ bk2, const float* __restrict__ Wv2,
        const float* __restrict__ bv2, const float* __restrict__ g1,
        const float* __restrict__ b1, const float* __restrict__ g2,
        const float* __restrict__ b2){
    __shared__ float xr[64];
    __shared__ float red[2];
    int row = blockIdx.x, t = threadIdx.x;
    int bh = row >> 6, s = row & 63;
    xr[t] = g_sumx2[row*64 + t];
    __syncthreads();
    #pragma unroll
    for (int pass=0; pass<2; pass++){
        const float* W  = pass ? Wv2 : Wk2;
        const float* bb = pass ? bv2 : bk2;
        const float* gg = pass ? g2  : g1;
        const float* bt = pass ? b2  : b1;
        float a = bb[t];
        #pragma unroll 8
        for (int j=0;j<64;j++) a += xr[j]*W[j*64+t];
        float sred = a;
        #pragma unroll
        for (int o=16;o;o>>=1) sred += __shfl_xor_sync(0xffffffffu, sred, o);
        if ((t&31)==0) red[t>>5] = sred;
        __syncthreads();
        float mean = (red[0]+red[1]) * (1.f/64.f);
        __syncthreads();
        float dv = a - mean;
        float v2 = dv*dv;
        #pragma unroll
        for (int o=16;o;o>>=1) v2 += __shfl_xor_sync(0xffffffffu, v2, o);
        if ((t&31)==0) red[t>>5] = v2;
        __syncthreads();
        float var = (red[0]+red[1]) * (1.f/64.f);
        __syncthreads();
        float outv = dv*rsqrtf(var+1e-5f)*gg[t] + bt[t];
        if (pass == 0)
            g_k2p[(size_t)row*64 + PERM8(t)] = cvt_tf32(outv);
        else
            g_v2t[((size_t)bh*64 + t)*64 + PERM8(s)] = cvt_tf32(outv);
    }
}

// ---------------------------------------------------------------------------
extern "C" void kernel_launch(void* const* d_in, const int* in_sizes, int n_in,
                              void* d_out, int out_size){
    const float* reg_x   = (const float*)d_in[0];
    const int*   tok     = (const int*)d_in[1];
    const int*   rel_idx = (const int*)d_in[2];
    const float* emb_sum  = (const float*)d_in[5];
    const float* rel_emb0 = (const float*)d_in[6];
    const float* Wq  = (const float*)d_in[7];  const float* bq  = (const float*)d_in[8];
    const float* Wk  = (const float*)d_in[9];  const float* bk  = (const float*)d_in[10];
    const float* Wv  = (const float*)d_in[11]; const float* bv  = (const float*)d_in[12];
    const float* Wr0 = (const float*)d_in[13]; const float* br0 = (const float*)d_in[14];
    const float* Wk2 = (const float*)d_in[15]; const float* bk2 = (const float*)d_in[16];
    const float* Wv2 = (const float*)d_in[17]; const float* bv2 = (const float*)d_in[18];
    const float* Wo  = (const float*)d_in[19]; const float* bo  = (const float*)d_in[20];
    const float* lnkg  = (const float*)d_in[21]; const float* lnkb  = (const float*)d_in[22];
    const float* lnvg  = (const float*)d_in[23]; const float* lnvb  = (const float*)d_in[24];
    const float* lnk2g = (const float*)d_in[25]; const float* lnk2b = (const float*)d_in[26];
    const float* lnv2g = (const float*)d_in[27]; const float* lnv2b = (const float*)d_in[28];
    float* out = (float*)d_out;

    cudaFuncSetAttribute(attn_sum_kernel,  cudaFuncAttributeMaxDynamicSharedMemorySize, ATTN_SMEM_BYTES);
    cudaFuncSetAttribute(attn_main_kernel, cudaFuncAttributeMaxDynamicSharedMemorySize, ATTN_SMEM_BYTES);
    cudaFuncSetAttribute(gemm_fused, cudaFuncAttributeMaxDynamicSharedMemorySize, GEMM_SMEM_BYTES);

    unsigned *xp, *attnp, *wqp, *wkp, *wvp, *wop;
    cudaGetSymbolAddress((void**)&xp, g_xp);
    cudaGetSymbolAddress((void**)&attnp, g_attnp);
    cudaGetSymbolAddress((void**)&wqp, g_Wqp);
    cudaGetSymbolAddress((void**)&wkp, g_Wkp);
    cudaGetSymbolAddress((void**)&wvp, g_Wvp);
    cudaGetSymbolAddress((void**)&wop, g_Wop);

    dim3 wgrid(32,32);
    dim3 wblk(32,8);
    dim3 ggrid(E_/128, MROWS/128);   // (8, 32)

    // Launch order puts gemm_fused(K) at position 6 for ncu capture (-s 5 -c 1).
    r0_kernel<<<Z_*H_, 64>>>(rel_emb0, Wr0, br0);                       // 1
    idx8_kernel<<<(B_*TOTLEN*R_/4 + 255)/256, 256>>>(rel_idx);          // 2
    cvtA_kernel<<<MROWS*E_/4/256, 256>>>(reg_x, xp);                    // 3
    cvtW_kernel<<<wgrid, wblk>>>(Wq, wqp);                              // 4
    cvtW_kernel<<<wgrid, wblk>>>(Wk, wkp);                              // 5
    gemm_fused<<<ggrid, 256, GEMM_SMEM_BYTES>>>(xp, wkp, bk, (float*)0, 1, lnkg, lnkb); // 6
    cvtW_kernel<<<wgrid, wblk>>>(Wv, wvp);                              // 7
    gemm_fused<<<ggrid, 256, GEMM_SMEM_BYTES>>>(xp, wvp, bv, (float*)0, 2, lnvg, lnvb); // 8
    gemm_fused<<<ggrid, 256, GEMM_SMEM_BYTES>>>(xp, wqp, bq, (float*)0, 0, (const float*)0, (const float*)0); // 9
    cvtW_kernel<<<wgrid, wblk>>>(Wo, wop);                              // 10

    attn_sum_kernel<<<dim3(B_*H_, SPLITS), 128, ATTN_SMEM_BYTES>>>(tok, emb_sum);
    combine_kernel<<<B_*H_*S_, 64>>>();
    k2v2_kernel<<<B_*H_*S_, 64>>>(Wk2, bk2, Wv2, bv2, lnk2g, lnk2b, lnv2g, lnv2b);

    attn_main_kernel<<<dim3(R_/64, H_, B_), 128, ATTN_SMEM_BYTES>>>();

    gemm_fused<<<ggrid, 256, GEMM_SMEM_BYTES>>>(attnp, wop, bo, out, 3, (const float*)0, (const float*)0);
}